// round 3
// baseline (speedup 1.0000x reference)
#include <cuda_runtime.h>
#include <math.h>

#define NROWS 20544     // B*L = 64*321
#define BB 64
#define LL 321
#define DD 512
#define DFFC 2048
#define HH 8
#define EE 64
#define NTOPK 10

// ---------------- scratch (allocation-free: __device__ globals) ----------------
__device__ float g_buf512[6ULL * NROWS * 512];    // six [NROWS,512] buffers
__device__ float g_buf2048[4ULL * NROWS * 2048];  // four [NROWS,2048] buffers

// ---------------- generic fp32 tiled GEMM: C = act(A@B + bias (+ res)) ----------
// A: [M,K] row-major, B: [K,N] row-major, K%16==0, N%128==0, M arbitrary.
// EP: 0=bias, 1=bias+relu, 2=bias+res+leaky(0.5), 3=bias+res+elu, 4=bias+res
template<int EP>
__global__ __launch_bounds__(256) void gemm_kernel(
    const float* __restrict__ A, const float* __restrict__ B,
    const float* __restrict__ bias, const float* __restrict__ res,
    float* __restrict__ C, int M, int N, int K)
{
    __shared__ float As[16][128];
    __shared__ float Bs[16][128];
    const int tid = threadIdx.x;
    const int bm = blockIdx.y * 128;
    const int bn = blockIdx.x * 128;
    const int ty = tid >> 4, tx = tid & 15;

    float acc[8][8];
#pragma unroll
    for (int i = 0; i < 8; i++)
#pragma unroll
        for (int j = 0; j < 8; j++) acc[i][j] = 0.f;

    const int arow0 = tid >> 2;        // 0..63
    const int acol  = (tid & 3) << 2;  // 0,4,8,12
    const int brow0 = tid >> 5;        // 0..7
    const int bcol  = (tid & 31) << 2;

    for (int k0 = 0; k0 < K; k0 += 16) {
#pragma unroll
        for (int t = 0; t < 2; t++) {
            int r = arow0 + t * 64;
            int grow = bm + r;
            float4 v = make_float4(0.f, 0.f, 0.f, 0.f);
            if (grow < M) v = *(const float4*)(A + (size_t)grow * K + k0 + acol);
            As[acol + 0][r] = v.x; As[acol + 1][r] = v.y;
            As[acol + 2][r] = v.z; As[acol + 3][r] = v.w;
        }
#pragma unroll
        for (int t = 0; t < 2; t++) {
            int r = brow0 + t * 8;
            *(float4*)&Bs[r][bcol] = *(const float4*)(B + (size_t)(k0 + r) * N + bn + bcol);
        }
        __syncthreads();
#pragma unroll
        for (int kk = 0; kk < 16; kk++) {
            float a[8], b[8];
#pragma unroll
            for (int i = 0; i < 8; i++) a[i] = As[kk][ty * 8 + i];
#pragma unroll
            for (int j = 0; j < 8; j++) b[j] = Bs[kk][tx * 8 + j];
#pragma unroll
            for (int i = 0; i < 8; i++)
#pragma unroll
                for (int j = 0; j < 8; j++) acc[i][j] = fmaf(a[i], b[j], acc[i][j]);
        }
        __syncthreads();
    }

#pragma unroll
    for (int i = 0; i < 8; i++) {
        int row = bm + ty * 8 + i;
        if (row < M) {
#pragma unroll
            for (int j = 0; j < 8; j++) {
                int col = bn + tx * 8 + j;
                float v = acc[i][j] + bias[col];
                if (EP == 2 || EP == 3 || EP == 4) v += res[(size_t)row * N + col];
                if (EP == 1) v = fmaxf(v, 0.f);
                if (EP == 2) v = (v > 0.f) ? v : 0.5f * v;
                if (EP == 3) v = (v > 0.f) ? v : expm1f(v);
                C[(size_t)row * N + col] = v;
            }
        }
    }
}

// ---------------- fp64-accumulate GEMM (exact), for q/k feeding top-k ------------
// 64x64 tile, 256 threads, 4x4 micro-tile with double accumulators.
// Output rounded to f32 (the best predictor of the reference's f32 tensor).
__global__ __launch_bounds__(256) void gemm64_kernel(
    const float* __restrict__ A, const float* __restrict__ B,
    const float* __restrict__ bias, float* __restrict__ C,
    int M, int N, int K, int relu)
{
    __shared__ double As[16][65];
    __shared__ double Bs[16][65];
    const int tid = threadIdx.x;
    const int bm = blockIdx.y * 64;
    const int bn = blockIdx.x * 64;
    const int ty = tid >> 4, tx = tid & 15;

    double acc[4][4];
#pragma unroll
    for (int i = 0; i < 4; i++)
#pragma unroll
        for (int j = 0; j < 4; j++) acc[i][j] = 0.0;

    const int ar = tid >> 2;          // 0..63
    const int ac = (tid & 3) << 2;    // 0,4,8,12
    const int br = tid >> 4;          // 0..15
    const int bc = (tid & 15) << 2;   // 0..60

    for (int k0 = 0; k0 < K; k0 += 16) {
        {
            int grow = bm + ar;
            float4 v = make_float4(0.f, 0.f, 0.f, 0.f);
            if (grow < M) v = *(const float4*)(A + (size_t)grow * K + k0 + ac);
            As[ac + 0][ar] = (double)v.x; As[ac + 1][ar] = (double)v.y;
            As[ac + 2][ar] = (double)v.z; As[ac + 3][ar] = (double)v.w;
        }
        {
            float4 v = *(const float4*)(B + (size_t)(k0 + br) * N + bn + bc);
            Bs[br][bc + 0] = (double)v.x; Bs[br][bc + 1] = (double)v.y;
            Bs[br][bc + 2] = (double)v.z; Bs[br][bc + 3] = (double)v.w;
        }
        __syncthreads();
#pragma unroll
        for (int kk = 0; kk < 16; kk++) {
            double a[4], b[4];
#pragma unroll
            for (int i = 0; i < 4; i++) a[i] = As[kk][ty * 4 + i];
#pragma unroll
            for (int j = 0; j < 4; j++) b[j] = Bs[kk][tx * 4 + j];
#pragma unroll
            for (int i = 0; i < 4; i++)
#pragma unroll
                for (int j = 0; j < 4; j++) acc[i][j] = fma(a[i], b[j], acc[i][j]);
        }
        __syncthreads();
    }

#pragma unroll
    for (int i = 0; i < 4; i++) {
        int row = bm + ty * 4 + i;
        if (row < M) {
#pragma unroll
            for (int j = 0; j < 4; j++) {
                int col = bn + tx * 4 + j;
                double v = acc[i][j] + (double)bias[col];
                if (relu && v < 0.0) v = 0.0;
                C[(size_t)row * N + col] = (float)v;
            }
        }
    }
}

// ---------------- batched scores (fp64 accumulate, exact): -----------------------
// S[bh,l,s] = sum_e q[b,l,h*64+e]*k[b,s,h*64+e]; grid (11,11,512), block 256
__global__ __launch_bounds__(256) void scores_kernel(
    const float* __restrict__ q, const float* __restrict__ k, float* __restrict__ out)
{
    int bh = blockIdx.z;
    int b = bh >> 3, h = bh & 7;
    int l0 = blockIdx.y * 32, s0 = blockIdx.x * 32;
    __shared__ double Qs[32][65];
    __shared__ double Ks[32][65];
    int tid = threadIdx.x;
    int r = tid >> 3;          // 0..31
    int c = (tid & 7) * 8;     // 0..56
    {
        int l = l0 + r;
        if (l < LL) {
            const float* src = q + ((size_t)(b * LL + l)) * DD + h * EE + c;
            float4 v0 = *(const float4*)src;
            float4 v1 = *(const float4*)(src + 4);
            Qs[r][c+0]=(double)v0.x; Qs[r][c+1]=(double)v0.y; Qs[r][c+2]=(double)v0.z; Qs[r][c+3]=(double)v0.w;
            Qs[r][c+4]=(double)v1.x; Qs[r][c+5]=(double)v1.y; Qs[r][c+6]=(double)v1.z; Qs[r][c+7]=(double)v1.w;
        } else {
#pragma unroll
            for (int t = 0; t < 8; t++) Qs[r][c+t] = 0.0;
        }
        int s = s0 + r;
        if (s < LL) {
            const float* src = k + ((size_t)(b * LL + s)) * DD + h * EE + c;
            float4 v0 = *(const float4*)src;
            float4 v1 = *(const float4*)(src + 4);
            Ks[r][c+0]=(double)v0.x; Ks[r][c+1]=(double)v0.y; Ks[r][c+2]=(double)v0.z; Ks[r][c+3]=(double)v0.w;
            Ks[r][c+4]=(double)v1.x; Ks[r][c+5]=(double)v1.y; Ks[r][c+6]=(double)v1.z; Ks[r][c+7]=(double)v1.w;
        } else {
#pragma unroll
            for (int t = 0; t < 8; t++) Ks[r][c+t] = 0.0;
        }
    }
    __syncthreads();
    int ty = tid >> 4, tx = tid & 15;
    double acc[2][2] = {{0.0,0.0},{0.0,0.0}};
#pragma unroll 4
    for (int kk = 0; kk < EE; kk++) {
        double a0 = Qs[ty*2+0][kk], a1 = Qs[ty*2+1][kk];
        double b0 = Ks[tx*2+0][kk], b1 = Ks[tx*2+1][kk];
        acc[0][0] = fma(a0, b0, acc[0][0]);
        acc[0][1] = fma(a0, b1, acc[0][1]);
        acc[1][0] = fma(a1, b0, acc[1][0]);
        acc[1][1] = fma(a1, b1, acc[1][1]);
    }
    size_t base = (size_t)bh * LL * LL;
#pragma unroll
    for (int i = 0; i < 2; i++) {
        int l = l0 + ty * 2 + i;
        if (l < LL) {
#pragma unroll
            for (int j = 0; j < 2; j++) {
                int s = s0 + tx * 2 + j;
                if (s < LL) out[base + (size_t)l * LL + s] = (float)acc[i][j];
            }
        }
    }
}

// ---------------- top-k mask + softmax, in place on scores ----------------
// warp per row; rows = 512*321 = 164352; block 256 = 8 warps; grid 20544
__global__ __launch_bounds__(256) void topk_softmax_kernel(float* __restrict__ A)
{
    const int lane = threadIdx.x & 31;
    const int wslot = threadIdx.x >> 5;
    const size_t row = (size_t)blockIdx.x * 8 + wslot;
    __shared__ float sm[8][352];
    float* s = sm[wslot];
    float* rp = A + row * LL;

    float r[11];
#pragma unroll
    for (int j = 0; j < 11; j++) {
        int idx = lane + j * 32;
        float v = (idx < LL) ? rp[idx] : -INFINITY;
        r[j] = v;
        s[idx] = v;
    }
    __syncwarp();

    float kth = 0.f, mmax = 0.f;
    for (int it = 0; it < NTOPK; it++) {
        float lm = -INFINITY;
#pragma unroll
        for (int j = 0; j < 11; j++) lm = fmaxf(lm, s[lane + j * 32]);
        float gm = lm;
#pragma unroll
        for (int o = 16; o > 0; o >>= 1) gm = fmaxf(gm, __shfl_xor_sync(0xffffffffu, gm, o));
        if (it == 0) mmax = gm;
        kth = gm;
        int li = 0x7fffffff;
#pragma unroll
        for (int j = 10; j >= 0; j--) {
            int idx = lane + j * 32;
            if (s[idx] == gm) li = idx;
        }
        int gi = li;
#pragma unroll
        for (int o = 16; o > 0; o >>= 1) gi = min(gi, __shfl_xor_sync(0xffffffffu, gi, o));
        if (li == gi) s[li] = -INFINITY;
        __syncwarp();
    }

    const float scale = 0.125f; // 1/sqrt(64)
    float e[11];
    float sum = 0.f;
#pragma unroll
    for (int j = 0; j < 11; j++) {
        int idx = lane + j * 32;
        float v = r[j];
        float t = (idx < LL && v >= kth) ? expf((v - mmax) * scale) : 0.f;
        e[j] = t;
        sum += t;
    }
#pragma unroll
    for (int o = 16; o > 0; o >>= 1) sum += __shfl_xor_sync(0xffffffffu, sum, o);
    float inv = 1.f / sum;
#pragma unroll
    for (int j = 0; j < 11; j++) {
        int idx = lane + j * 32;
        if (idx < LL) rp[idx] = e[j] * inv;
    }
}

// ---------------- A @ V:  out[b,l,h*64+e] = sum_s A[bh,l,s] * v[b,s,h*64+e] ---------
__global__ __launch_bounds__(256) void av_kernel(
    const float* __restrict__ A, const float* __restrict__ v, float* __restrict__ out)
{
    int bh = blockIdx.z;
    int b = bh >> 3, h = bh & 7;
    int l0 = blockIdx.y * 64;
    __shared__ float As2[64][17];
    __shared__ float Vs[16][65];
    int tid = threadIdx.x;
    int ty = tid >> 4, tx = tid & 15;
    float acc[4][4];
#pragma unroll
    for (int i = 0; i < 4; i++)
#pragma unroll
        for (int j = 0; j < 4; j++) acc[i][j] = 0.f;

    const int ar = tid >> 2, ac = (tid & 3) * 4;   // A tile load
    const int vr = tid >> 4, vc = (tid & 15) * 4;  // V tile load
    size_t abase = (size_t)bh * LL * LL;

    for (int s0 = 0; s0 < LL; s0 += 16) {
        int l = l0 + ar;
#pragma unroll
        for (int cc = 0; cc < 4; cc++) {
            int sidx = s0 + ac + cc;
            As2[ar][ac + cc] = (l < LL && sidx < LL) ? A[abase + (size_t)l * LL + sidx] : 0.f;
        }
        int sv = s0 + vr;
        if (sv < LL) {
            float4 t = *(const float4*)(v + ((size_t)(b * LL + sv)) * DD + h * EE + vc);
            Vs[vr][vc+0]=t.x; Vs[vr][vc+1]=t.y; Vs[vr][vc+2]=t.z; Vs[vr][vc+3]=t.w;
        } else {
#pragma unroll
            for (int t = 0; t < 4; t++) Vs[vr][vc+t] = 0.f;
        }
        __syncthreads();
#pragma unroll
        for (int kk = 0; kk < 16; kk++) {
            float a[4], bb2[4];
#pragma unroll
            for (int i = 0; i < 4; i++) a[i] = As2[ty*4+i][kk];
#pragma unroll
            for (int j = 0; j < 4; j++) bb2[j] = Vs[kk][tx*4+j];
#pragma unroll
            for (int i = 0; i < 4; i++)
#pragma unroll
                for (int j = 0; j < 4; j++) acc[i][j] = fmaf(a[i], bb2[j], acc[i][j]);
        }
        __syncthreads();
    }
#pragma unroll
    for (int i = 0; i < 4; i++) {
        int l = l0 + ty * 4 + i;
        if (l < LL) {
#pragma unroll
            for (int j = 0; j < 4; j++) {
                int e = tx * 4 + j;
                out[((size_t)(b * LL + l)) * DD + h * EE + e] = acc[i][j];
            }
        }
    }
}

// ---------------- pwattn1 core: per row n, q[128,16], k/v[32,16] ----------------
__global__ __launch_bounds__(128) void pwattn1_kernel(
    const float* __restrict__ q, const float* __restrict__ k,
    const float* __restrict__ v, float* __restrict__ out)
{
    int n = blockIdx.x;
    int l = threadIdx.x;
    __shared__ float sk[512];
    __shared__ float sv[512];
    int t4 = l * 4;
    *(float4*)&sk[t4] = *(const float4*)(k + (size_t)n * 512 + t4);
    *(float4*)&sv[t4] = *(const float4*)(v + (size_t)n * 512 + t4);
    __syncthreads();
    float qr[16];
    const float* qp = q + (size_t)n * 2048 + l * 16;
#pragma unroll
    for (int p = 0; p < 16; p++) qr[p] = qp[p];
    float sc[32];
    float m = -INFINITY;
#pragma unroll
    for (int s = 0; s < 32; s++) {
        float d = 0.f;
#pragma unroll
        for (int p = 0; p < 16; p++) d = fmaf(qr[p], sk[s * 16 + p], d);
        sc[s] = d;
        m = fmaxf(m, d);
    }
    float sum = 0.f;
    float V[16];
#pragma unroll
    for (int p = 0; p < 16; p++) V[p] = 0.f;
#pragma unroll
    for (int s = 0; s < 32; s++) {
        float w = expf((sc[s] - m) * 0.25f);
        sum += w;
#pragma unroll
        for (int p = 0; p < 16; p++) V[p] = fmaf(w, sv[s * 16 + p], V[p]);
    }
    float inv = 1.f / sum;
    float* op = out + (size_t)n * 2048 + l * 16;
#pragma unroll
    for (int p = 0; p < 16; p++) op[p] = V[p] * inv;
}

// ---------------- pwattn2 core: per row n, q[32,16], k/v[128,16] ----------------
__global__ __launch_bounds__(128) void pwattn2_kernel(
    const float* __restrict__ q, const float* __restrict__ k2,
    const float* __restrict__ v2, float* __restrict__ out)
{
    int n = blockIdx.x * 4 + (threadIdx.x >> 5);
    int lane = threadIdx.x & 31;
    const float* kp = k2 + (size_t)n * 2048;
    const float* vp = v2 + (size_t)n * 2048;
    float qr[16];
    const float* qp = q + (size_t)n * 512 + lane * 16;
#pragma unroll
    for (int p = 0; p < 16; p++) qr[p] = qp[p];
    float m = -INFINITY;
    for (int s = 0; s < 128; s++) {
        float d = 0.f;
#pragma unroll
        for (int p = 0; p < 16; p++) d = fmaf(qr[p], kp[s * 16 + p], d);
        m = fmaxf(m, d);
    }
    float sum = 0.f;
    float V[16];
#pragma unroll
    for (int p = 0; p < 16; p++) V[p] = 0.f;
    for (int s = 0; s < 128; s++) {
        float d = 0.f;
#pragma unroll
        for (int p = 0; p < 16; p++) d = fmaf(qr[p], kp[s * 16 + p], d);
        float w = expf((d - m) * 0.25f);
        sum += w;
#pragma unroll
        for (int p = 0; p < 16; p++) V[p] = fmaf(w, vp[s * 16 + p], V[p]);
    }
    float inv = 1.f / sum;
    float* op = out + (size_t)n * 512 + lane * 16;
#pragma unroll
    for (int p = 0; p < 16; p++) op[p] = V[p] * inv;
}

// ---------------- layernorm over 2048 ----------------
__global__ __launch_bounds__(256) void ln_kernel(
    const float* __restrict__ in, const float* __restrict__ g,
    const float* __restrict__ b, float* __restrict__ out)
{
    int n = blockIdx.x;
    int tid = threadIdx.x;
    __shared__ float red[256];
    const float* x = in + (size_t)n * 2048;
    float s = 0.f;
    for (int i = tid; i < 2048; i += 256) s += x[i];
    red[tid] = s; __syncthreads();
    for (int o = 128; o > 0; o >>= 1) { if (tid < o) red[tid] += red[tid + o]; __syncthreads(); }
    float mean = red[0] * (1.f / 2048.f);
    __syncthreads();
    float vs = 0.f;
    for (int i = tid; i < 2048; i += 256) { float d = x[i] - mean; vs += d * d; }
    red[tid] = vs; __syncthreads();
    for (int o = 128; o > 0; o >>= 1) { if (tid < o) red[tid] += red[tid + o]; __syncthreads(); }
    float var = red[0] * (1.f / 2048.f);
    float inv = rsqrtf(var + 1e-5f);
    float* op = out + (size_t)n * 2048;
    for (int i = tid; i < 2048; i += 256) op[i] = (x[i] - mean) * inv * g[i] + b[i];
}

// ---------------- launch ----------------
extern "C" void kernel_launch(void* const* d_in, const int* in_sizes, int n_in,
                              void* d_out, int out_size)
{
    (void)in_sizes; (void)n_in; (void)out_size;
    const float* x     = (const float*)d_in[0];
    const float* aqw   = (const float*)d_in[1];
    const float* aqb   = (const float*)d_in[2];
    const float* akw   = (const float*)d_in[3];
    const float* akb   = (const float*)d_in[4];
    const float* avw   = (const float*)d_in[5];
    const float* avb   = (const float*)d_in[6];
    const float* aow   = (const float*)d_in[7];
    const float* aob   = (const float*)d_in[8];
    const float* encw  = (const float*)d_in[9];
    const float* encb  = (const float*)d_in[10];
    const float* f1qw  = (const float*)d_in[11];
    const float* f1qb  = (const float*)d_in[12];
    const float* f1kw  = (const float*)d_in[13];
    const float* f1kb  = (const float*)d_in[14];
    const float* f1vw  = (const float*)d_in[15];
    const float* f1vb  = (const float*)d_in[16];
    const float* f1ow  = (const float*)d_in[17];
    const float* f1ob  = (const float*)d_in[18];
    const float* f2qw  = (const float*)d_in[19];
    const float* f2qb  = (const float*)d_in[20];
    const float* f2kw  = (const float*)d_in[21];
    const float* f2kb  = (const float*)d_in[22];
    const float* f2vw  = (const float*)d_in[23];
    const float* f2vb  = (const float*)d_in[24];
    const float* f2ow  = (const float*)d_in[25];
    const float* f2ob  = (const float*)d_in[26];
    const float* lng   = (const float*)d_in[27];
    const float* lnb   = (const float*)d_in[28];

    float* out  = (float*)d_out;
    float* Aout = out + (size_t)NROWS * 512;   // [B,H,L,L] region

    float* b512;  float* b2048;
    cudaGetSymbolAddress((void**)&b512,  g_buf512);
    cudaGetSymbolAddress((void**)&b2048, g_buf2048);
    const size_t S = (size_t)NROWS * 512;
    const size_t T = (size_t)NROWS * 2048;
    float* qb   = b512;             // q buffer, later k1
    float* kb   = b512 + S;         // k buffer, later v1
    float* vb   = b512 + 2 * S;     // v buffer, later query2
    float* att  = b512 + 3 * S;     // attn out, later Vflat2
    float* zb   = b512 + 4 * S;     // leaky(x+attn@Wo+b)
    float* y2   = b512 + 5 * S;     // enc output
    float* q1   = b2048;            // query1, later k2
    float* Vf1  = b2048 + T;        // pwattn1 V, later v2
    float* t1   = b2048 + 2 * T;    // elu(out1)
    float* u    = b2048 + 3 * T;    // layernorm out

    dim3 blk(256);
    auto g512  = dim3(4, (NROWS + 127) / 128);
    auto g2048 = dim3(16, (NROWS + 127) / 128);
    auto g64   = dim3(8, (NROWS + 63) / 64);   // fp64 gemm: 64x64 tiles, N=512

    // ---- graph attention (q,k,scores on exact fp64 path: feeds top-k) ----
    gemm64_kernel<<<g64, blk>>>(x, aqw, aqb, qb, NROWS, 512, 512, 1);  // q = relu(...)
    gemm64_kernel<<<g64, blk>>>(x, akw, akb, kb, NROWS, 512, 512, 0);  // k
    gemm_kernel<1><<<g512, blk>>>(x, avw, avb, nullptr, vb, NROWS, 512, 512);
    scores_kernel<<<dim3(11, 11, 512), blk>>>(qb, kb, Aout);
    topk_softmax_kernel<<<20544, blk>>>(Aout);
    av_kernel<<<dim3(1, 6, 512), blk>>>(Aout, vb, att);
    gemm_kernel<2><<<g512, blk>>>(att, aow, aob, x, zb, NROWS, 512, 512);     // leaky(x + attn_o)
    gemm_kernel<0><<<g512, blk>>>(zb, encw, encb, nullptr, y2, NROWS, 512, 512);

    // ---- ff1 pwattn ----
    gemm_kernel<1><<<g2048, blk>>>(y2, f1qw, f1qb, nullptr, q1, NROWS, 2048, 512);
    gemm_kernel<0><<<g512, blk>>>(y2, f1kw, f1kb, nullptr, qb, NROWS, 512, 512);   // k1
    gemm_kernel<1><<<g512, blk>>>(y2, f1vw, f1vb, nullptr, kb, NROWS, 512, 512);   // v1
    pwattn1_kernel<<<NROWS, 128>>>(q1, qb, kb, Vf1);
    gemm_kernel<3><<<g2048, blk>>>(Vf1, f1ow, f1ob, q1, t1, NROWS, 2048, 2048);    // elu(query + V@Wo)
    ln_kernel<<<NROWS, blk>>>(t1, lng, lnb, u);

    // ---- ff2 pwattn ----
    gemm_kernel<1><<<g512, blk>>>(u, f2qw, f2qb, nullptr, vb, NROWS, 512, 2048);   // query2
    gemm_kernel<0><<<g2048, blk>>>(u, f2kw, f2kb, nullptr, q1, NROWS, 2048, 2048); // k2
    gemm_kernel<1><<<g2048, blk>>>(u, f2vw, f2vb, nullptr, Vf1, NROWS, 2048, 2048);// v2
    pwattn2_kernel<<<NROWS / 4, 128>>>(vb, q1, Vf1, att);                          // Vflat2
    gemm_kernel<4><<<g512, blk>>>(att, f2ow, f2ob, vb, out, NROWS, 512, 512);      // y out
}

// round 6
// speedup vs baseline: 1.0663x; 1.0663x over previous
#include <cuda_runtime.h>
#include <math.h>
#include <stdint.h>

#define NROWS 20544     // B*L = 64*321
#define LL 321
#define DD 512
#define HH 8
#define EE 64
#define NTOPK 10

// ---------------- scratch (allocation-free: __device__ globals) ----------------
__device__ float g_buf512[6ULL * NROWS * 512];
__device__ float g_buf2048[4ULL * NROWS * 2048];
__device__ float g_wt[16252928];   // transposed weights [N,K]

#define OFF_AV   0u
#define OFF_AO   262144u
#define OFF_ENC  524288u
#define OFF_F1Q  786432u
#define OFF_F1K  1835008u
#define OFF_F1V  2097152u
#define OFF_F1O  2359296u
#define OFF_F2Q  6553600u
#define OFF_F2K  7602176u
#define OFF_F2V  11796480u
#define OFF_F2O  15990784u

// ============================ weight transpose =================================
// src [K,N] row-major -> dst [N,K] row-major
__global__ void transpose_kernel(const float* __restrict__ src, float* __restrict__ dst,
                                 int K, int N)
{
    __shared__ float t[32][33];
    int bx = blockIdx.x * 32, by = blockIdx.y * 32;
    int txi = threadIdx.x, tyi = threadIdx.y;
#pragma unroll
    for (int j = 0; j < 32; j += 8)
        t[tyi + j][txi] = src[(size_t)(by + tyi + j) * N + bx + txi];
    __syncthreads();
#pragma unroll
    for (int j = 0; j < 32; j += 8)
        dst[(size_t)(bx + tyi + j) * K + by + txi] = t[txi][tyi + j];
}

// ================= 3xTF32 mma.sync GEMM (fp32-accurate, tensor cores) ==========
// C[M,N] = act(A[M,K] @ Bt[N,K]^T + bias (+res));  N%128==0, K%32==0.
// EP: 0=bias, 1=bias+relu, 2=bias+res+leaky(0.5), 3=bias+res+elu, 4=bias+res
// Tile 128x128x32; 256 threads = 8 warps (2 m x 4 n), warp tile 64x32.
#define MM_PITCH 36                      // floats per smem row (32 + 4 pad)
#define MM_HALF  (128 * MM_PITCH)        // floats per A (or B) stage part
#define MM_STAGE (2 * MM_HALF)           // floats per stage (A + B)
#define MM_SMEM  (2 * MM_STAGE * 4)      // bytes, 2 stages

__device__ __forceinline__ void split_tf32(float x, uint32_t& hi, uint32_t& lo) {
    float h, l;
    asm("cvt.rna.tf32.f32 %0, %1;" : "=f"(h) : "f"(x));
    l = x - h;                       // exact in fp32
    asm("cvt.rna.tf32.f32 %0, %1;" : "=f"(l) : "f"(l));
    hi = __float_as_uint(h);
    lo = __float_as_uint(l);
}

__device__ __forceinline__ void mm_load_stage(
    const float* __restrict__ A, const float* __restrict__ Bt,
    int bm, int bn, int M, int K, int k0, float* st, int tid)
{
    uint32_t a_s, b_s;
    asm("{ .reg .u64 t; cvta.to.shared.u64 t, %1; cvt.u32.u64 %0, t; }" : "=r"(a_s) : "l"(st));
    b_s = a_s + MM_HALF * 4;
#pragma unroll
    for (int j = 0; j < 4; j++) {
        int idx = tid + j * 256;
        int r = idx >> 3, c = idx & 7;
        uint32_t doff = (uint32_t)(r * MM_PITCH + c * 4) * 4;
        int grow = bm + r;
        const float* srcA = A + (size_t)(grow < M ? grow : 0) * K + k0 + c * 4;
        int szA = (grow < M) ? 16 : 0;
        asm volatile("cp.async.ca.shared.global [%0], [%1], 16, %2;"
                     :: "r"(a_s + doff), "l"(srcA), "r"(szA));
        const float* srcB = Bt + (size_t)(bn + r) * K + k0 + c * 4;
        asm volatile("cp.async.ca.shared.global [%0], [%1], 16;"
                     :: "r"(b_s + doff), "l"(srcB));
    }
    asm volatile("cp.async.commit_group;" ::: "memory");
}

#define MMA_TF32(acc, a0, a1, a2, a3, b0, b1) \
    asm volatile( \
        "mma.sync.aligned.m16n8k8.row.col.f32.tf32.tf32.f32 " \
        "{%0,%1,%2,%3}, {%4,%5,%6,%7}, {%8,%9}, {%0,%1,%2,%3};" \
        : "+f"((acc)[0]), "+f"((acc)[1]), "+f"((acc)[2]), "+f"((acc)[3]) \
        : "r"(a0), "r"(a1), "r"(a2), "r"(a3), "r"(b0), "r"(b1))

template<int EP>
__global__ __launch_bounds__(256)
void mm_gemm_kernel(const float* __restrict__ A, const float* __restrict__ Bt,
                    const float* __restrict__ bias, const float* __restrict__ res,
                    float* __restrict__ C, int M, int N, int K)
{
    extern __shared__ float sm[];
    const int tid = threadIdx.x;
    const int wid = tid >> 5, lane = tid & 31;
    const int wm = wid >> 2, wn = wid & 3;     // 2 x 4 warps
    const int g = lane >> 2, t = lane & 3;
    const int bm = blockIdx.y * 128, bn = blockIdx.x * 128;

    float acc[4][4][4];
#pragma unroll
    for (int i = 0; i < 4; i++)
#pragma unroll
        for (int j = 0; j < 4; j++)
#pragma unroll
            for (int q = 0; q < 4; q++) acc[i][j][q] = 0.f;

    const int nc = K >> 5;
    mm_load_stage(A, Bt, bm, bn, M, K, 0, sm, tid);

    for (int c = 0; c < nc; c++) {
        if (c + 1 < nc)
            mm_load_stage(A, Bt, bm, bn, M, K, (c + 1) * 32, sm + ((c + 1) & 1) * MM_STAGE, tid);
        if (c + 1 < nc) asm volatile("cp.async.wait_group 1;" ::: "memory");
        else            asm volatile("cp.async.wait_group 0;" ::: "memory");
        __syncthreads();

        const float* As = sm + (c & 1) * MM_STAGE;
        const float* Bs = As + MM_HALF;
#pragma unroll
        for (int kk = 0; kk < 4; kk++) {
            int k0 = kk * 8;
            uint32_t ah[4][4], al[4][4], bh[4][2], bl[4][2];
#pragma unroll
            for (int mt = 0; mt < 4; mt++) {
                int m = wm * 64 + mt * 16 + g;
                split_tf32(As[m * MM_PITCH + k0 + t],           ah[mt][0], al[mt][0]);
                split_tf32(As[(m + 8) * MM_PITCH + k0 + t],     ah[mt][1], al[mt][1]);
                split_tf32(As[m * MM_PITCH + k0 + t + 4],       ah[mt][2], al[mt][2]);
                split_tf32(As[(m + 8) * MM_PITCH + k0 + t + 4], ah[mt][3], al[mt][3]);
            }
#pragma unroll
            for (int nt = 0; nt < 4; nt++) {
                int n = wn * 32 + nt * 8 + g;
                split_tf32(Bs[n * MM_PITCH + k0 + t],     bh[nt][0], bl[nt][0]);
                split_tf32(Bs[n * MM_PITCH + k0 + t + 4], bh[nt][1], bl[nt][1]);
            }
#pragma unroll
            for (int mt = 0; mt < 4; mt++)
#pragma unroll
                for (int nt = 0; nt < 4; nt++) {
                    MMA_TF32(acc[mt][nt], al[mt][0], al[mt][1], al[mt][2], al[mt][3],
                             bh[nt][0], bh[nt][1]);
                    MMA_TF32(acc[mt][nt], ah[mt][0], ah[mt][1], ah[mt][2], ah[mt][3],
                             bl[nt][0], bl[nt][1]);
                    MMA_TF32(acc[mt][nt], ah[mt][0], ah[mt][1], ah[mt][2], ah[mt][3],
                             bh[nt][0], bh[nt][1]);
                }
        }
        __syncthreads();
    }

    // epilogue: d0,d1 -> (row g, cols t*2,t*2+1); d2,d3 -> row g+8
#pragma unroll
    for (int mt = 0; mt < 4; mt++) {
#pragma unroll
        for (int half = 0; half < 2; half++) {
            int row = bm + wm * 64 + mt * 16 + g + half * 8;
            if (row >= M) continue;
#pragma unroll
            for (int nt = 0; nt < 4; nt++) {
                int col = bn + wn * 32 + nt * 8 + t * 2;
                float v0 = acc[mt][nt][half * 2 + 0] + bias[col];
                float v1 = acc[mt][nt][half * 2 + 1] + bias[col + 1];
                if (EP >= 2) {
                    v0 += res[(size_t)row * N + col];
                    v1 += res[(size_t)row * N + col + 1];
                }
                if (EP == 1) { v0 = fmaxf(v0, 0.f); v1 = fmaxf(v1, 0.f); }
                if (EP == 2) { v0 = (v0 > 0.f) ? v0 : 0.5f * v0; v1 = (v1 > 0.f) ? v1 : 0.5f * v1; }
                if (EP == 3) { v0 = (v0 > 0.f) ? v0 : expm1f(v0); v1 = (v1 > 0.f) ? v1 : expm1f(v1); }
                float2 o = make_float2(v0, v1);
                *(float2*)(C + (size_t)row * N + col) = o;
            }
        }
    }
}

// ---------------- fp64-accumulate GEMM (exact), q/k feeding top-k ---------------
__global__ __launch_bounds__(256) void gemm64_kernel(
    const float* __restrict__ A, const float* __restrict__ B,
    const float* __restrict__ bias, float* __restrict__ C,
    int M, int N, int K, int relu)
{
    __shared__ double As[16][65];
    __shared__ double Bs[16][65];
    const int tid = threadIdx.x;
    const int bm = blockIdx.y * 64;
    const int bn = blockIdx.x * 64;
    const int ty = tid >> 4, tx = tid & 15;

    double acc[4][4];
#pragma unroll
    for (int i = 0; i < 4; i++)
#pragma unroll
        for (int j = 0; j < 4; j++) acc[i][j] = 0.0;

    const int ar = tid >> 2;
    const int ac = (tid & 3) << 2;
    const int br = tid >> 4;
    const int bc = (tid & 15) << 2;

    for (int k0 = 0; k0 < K; k0 += 16) {
        {
            int grow = bm + ar;
            float4 v = make_float4(0.f, 0.f, 0.f, 0.f);
            if (grow < M) v = *(const float4*)(A + (size_t)grow * K + k0 + ac);
            As[ac + 0][ar] = (double)v.x; As[ac + 1][ar] = (double)v.y;
            As[ac + 2][ar] = (double)v.z; As[ac + 3][ar] = (double)v.w;
        }
        {
            float4 v = *(const float4*)(B + (size_t)(k0 + br) * N + bn + bc);
            Bs[br][bc + 0] = (double)v.x; Bs[br][bc + 1] = (double)v.y;
            Bs[br][bc + 2] = (double)v.z; Bs[br][bc + 3] = (double)v.w;
        }
        __syncthreads();
#pragma unroll
        for (int kk = 0; kk < 16; kk++) {
            double a[4], b[4];
#pragma unroll
            for (int i = 0; i < 4; i++) a[i] = As[kk][ty * 4 + i];
#pragma unroll
            for (int j = 0; j < 4; j++) b[j] = Bs[kk][tx * 4 + j];
#pragma unroll
            for (int i = 0; i < 4; i++)
#pragma unroll
                for (int j = 0; j < 4; j++) acc[i][j] = fma(a[i], b[j], acc[i][j]);
        }
        __syncthreads();
    }

#pragma unroll
    for (int i = 0; i < 4; i++) {
        int row = bm + ty * 4 + i;
        if (row < M) {
#pragma unroll
            for (int j = 0; j < 4; j++) {
                int col = bn + tx * 4 + j;
                double v = acc[i][j] + (double)bias[col];
                if (relu && v < 0.0) v = 0.0;
                C[(size_t)row * N + col] = (float)v;
            }
        }
    }
}

// ---------------- batched scores (fp64 accumulate, exact) -----------------------
__global__ __launch_bounds__(256) void scores_kernel(
    const float* __restrict__ q, const float* __restrict__ k, float* __restrict__ out)
{
    int bh = blockIdx.z;
    int b = bh >> 3, h = bh & 7;
    int l0 = blockIdx.y * 32, s0 = blockIdx.x * 32;
    __shared__ double Qs[32][65];
    __shared__ double Ks[32][65];
    int tid = threadIdx.x;
    int r = tid >> 3;
    int c = (tid & 7) * 8;
    {
        int l = l0 + r;
        if (l < LL) {
            const float* src = q + ((size_t)(b * LL + l)) * DD + h * EE + c;
            float4 v0 = *(const float4*)src;
            float4 v1 = *(const float4*)(src + 4);
            Qs[r][c+0]=(double)v0.x; Qs[r][c+1]=(double)v0.y; Qs[r][c+2]=(double)v0.z; Qs[r][c+3]=(double)v0.w;
            Qs[r][c+4]=(double)v1.x; Qs[r][c+5]=(double)v1.y; Qs[r][c+6]=(double)v1.z; Qs[r][c+7]=(double)v1.w;
        } else {
#pragma unroll
            for (int t = 0; t < 8; t++) Qs[r][c+t] = 0.0;
        }
        int s = s0 + r;
        if (s < LL) {
            const float* src = k + ((size_t)(b * LL + s)) * DD + h * EE + c;
            float4 v0 = *(const float4*)src;
            float4 v1 = *(const float4*)(src + 4);
            Ks[r][c+0]=(double)v0.x; Ks[r][c+1]=(double)v0.y; Ks[r][c+2]=(double)v0.z; Ks[r][c+3]=(double)v0.w;
            Ks[r][c+4]=(double)v1.x; Ks[r][c+5]=(double)v1.y; Ks[r][c+6]=(double)v1.z; Ks[r][c+7]=(double)v1.w;
        } else {
#pragma unroll
            for (int t = 0; t < 8; t++) Ks[r][c+t] = 0.0;
        }
    }
    __syncthreads();
    int ty = tid >> 4, tx = tid & 15;
    double acc[2][2] = {{0.0,0.0},{0.0,0.0}};
#pragma unroll 4
    for (int kk = 0; kk < EE; kk++) {
        double a0 = Qs[ty*2+0][kk], a1 = Qs[ty*2+1][kk];
        double b0 = Ks[tx*2+0][kk], b1 = Ks[tx*2+1][kk];
        acc[0][0] = fma(a0, b0, acc[0][0]);
        acc[0][1] = fma(a0, b1, acc[0][1]);
        acc[1][0] = fma(a1, b0, acc[1][0]);
        acc[1][1] = fma(a1, b1, acc[1][1]);
    }
    size_t base = (size_t)bh * LL * LL;
#pragma unroll
    for (int i = 0; i < 2; i++) {
        int l = l0 + ty * 2 + i;
        if (l < LL) {
#pragma unroll
            for (int j = 0; j < 2; j++) {
                int s = s0 + tx * 2 + j;
                if (s < LL) out[base + (size_t)l * LL + s] = (float)acc[i][j];
            }
        }
    }
}

// ---------------- top-k mask + softmax, in place on scores ----------------
__global__ __launch_bounds__(256) void topk_softmax_kernel(float* __restrict__ A)
{
    const int lane = threadIdx.x & 31;
    const int wslot = threadIdx.x >> 5;
    const size_t row = (size_t)blockIdx.x * 8 + wslot;
    __shared__ float sm[8][352];
    float* s = sm[wslot];
    float* rp = A + row * LL;

    float r[11];
#pragma unroll
    for (int j = 0; j < 11; j++) {
        int idx = lane + j * 32;
        float v = (idx < LL) ? rp[idx] : -INFINITY;
        r[j] = v;
        s[idx] = v;
    }
    __syncwarp();

    float kth = 0.f, mmax = 0.f;
    for (int it = 0; it < NTOPK; it++) {
        float lm = -INFINITY;
#pragma unroll
        for (int j = 0; j < 11; j++) lm = fmaxf(lm, s[lane + j * 32]);
        float gm = lm;
#pragma unroll
        for (int o = 16; o > 0; o >>= 1) gm = fmaxf(gm, __shfl_xor_sync(0xffffffffu, gm, o));
        if (it == 0) mmax = gm;
        kth = gm;
        int li = 0x7fffffff;
#pragma unroll
        for (int j = 10; j >= 0; j--) {
            int idx = lane + j * 32;
            if (s[idx] == gm) li = idx;
        }
        int gi = li;
#pragma unroll
        for (int o = 16; o > 0; o >>= 1) gi = min(gi, __shfl_xor_sync(0xffffffffu, gi, o));
        if (li == gi) s[li] = -INFINITY;
        __syncwarp();
    }

    const float scale = 0.125f;
    float e[11];
    float sum = 0.f;
#pragma unroll
    for (int j = 0; j < 11; j++) {
        int idx = lane + j * 32;
        float v = r[j];
        float t = (idx < LL && v >= kth) ? expf((v - mmax) * scale) : 0.f;
        e[j] = t;
        sum += t;
    }
#pragma unroll
    for (int o = 16; o > 0; o >>= 1) sum += __shfl_xor_sync(0xffffffffu, sum, o);
    float inv = 1.f / sum;
#pragma unroll
    for (int j = 0; j < 11; j++) {
        int idx = lane + j * 32;
        if (idx < LL) rp[idx] = e[j] * inv;
    }
}

// ---------------- A @ V ---------------------------------------------------------
__global__ __launch_bounds__(256) void av_kernel(
    const float* __restrict__ A, const float* __restrict__ v, float* __restrict__ out)
{
    int bh = blockIdx.z;
    int b = bh >> 3, h = bh & 7;
    int l0 = blockIdx.y * 64;
    __shared__ float As2[64][17];
    __shared__ float Vs[16][65];
    int tid = threadIdx.x;
    int ty = tid >> 4, tx = tid & 15;
    float acc[4][4];
#pragma unroll
    for (int i = 0; i < 4; i++)
#pragma unroll
        for (int j = 0; j < 4; j++) acc[i][j] = 0.f;

    const int ar = tid >> 2, ac = (tid & 3) * 4;
    const int vr = tid >> 4, vc = (tid & 15) * 4;
    size_t abase = (size_t)bh * LL * LL;

    for (int s0 = 0; s0 < LL; s0 += 16) {
        int l = l0 + ar;
#pragma unroll
        for (int cc = 0; cc < 4; cc++) {
            int sidx = s0 + ac + cc;
            As2[ar][ac + cc] = (l < LL && sidx < LL) ? A[abase + (size_t)l * LL + sidx] : 0.f;
        }
        int sv = s0 + vr;
        if (sv < LL) {
            float4 t = *(const float4*)(v + ((size_t)(b * LL + sv)) * DD + h * EE + vc);
            Vs[vr][vc+0]=t.x; Vs[vr][vc+1]=t.y; Vs[vr][vc+2]=t.z; Vs[vr][vc+3]=t.w;
        } else {
#pragma unroll
            for (int t = 0; t < 4; t++) Vs[vr][vc+t] = 0.f;
        }
        __syncthreads();
#pragma unroll
        for (int kk = 0; kk < 16; kk++) {
            float a[4], bb2[4];
#pragma unroll
            for (int i = 0; i < 4; i++) a[i] = As2[ty*4+i][kk];
#pragma unroll
            for (int j = 0; j < 4; j++) bb2[j] = Vs[kk][tx*4+j];
#pragma unroll
            for (int i = 0; i < 4; i++)
#pragma unroll
                for (int j = 0; j < 4; j++) acc[i][j] = fmaf(a[i], bb2[j], acc[i][j]);
        }
        __syncthreads();
    }
#pragma unroll
    for (int i = 0; i < 4; i++) {
        int l = l0 + ty * 4 + i;
        if (l < LL) {
#pragma unroll
            for (int j = 0; j < 4; j++) {
                int e = tx * 4 + j;
                out[((size_t)(b * LL + l)) * DD + h * EE + e] = acc[i][j];
            }
        }
    }
}

// ---------------- pwattn1 -------------------------------------------------------
__global__ __launch_bounds__(128) void pwattn1_kernel(
    const float* __restrict__ q, const float* __restrict__ k,
    const float* __restrict__ v, float* __restrict__ out)
{
    int n = blockIdx.x;
    int l = threadIdx.x;
    __shared__ float sk[512];
    __shared__ float sv[512];
    int t4 = l * 4;
    *(float4*)&sk[t4] = *(const float4*)(k + (size_t)n * 512 + t4);
    *(float4*)&sv[t4] = *(const float4*)(v + (size_t)n * 512 + t4);
    __syncthreads();
    float qr[16];
    const float* qp = q + (size_t)n * 2048 + l * 16;
#pragma unroll
    for (int p = 0; p < 16; p++) qr[p] = qp[p];
    float sc[32];
    float m = -INFINITY;
#pragma unroll
    for (int s = 0; s < 32; s++) {
        float d = 0.f;
#pragma unroll
        for (int p = 0; p < 16; p++) d = fmaf(qr[p], sk[s * 16 + p], d);
        sc[s] = d;
        m = fmaxf(m, d);
    }
    float sum = 0.f;
    float V[16];
#pragma unroll
    for (int p = 0; p < 16; p++) V[p] = 0.f;
#pragma unroll
    for (int s = 0; s < 32; s++) {
        float w = expf((sc[s] - m) * 0.25f);
        sum += w;
#pragma unroll
        for (int p = 0; p < 16; p++) V[p] = fmaf(w, sv[s * 16 + p], V[p]);
    }
    float inv = 1.f / sum;
    float* op = out + (size_t)n * 2048 + l * 16;
#pragma unroll
    for (int p = 0; p < 16; p++) op[p] = V[p] * inv;
}

// ---------------- pwattn2 -------------------------------------------------------
__global__ __launch_bounds__(128) void pwattn2_kernel(
    const float* __restrict__ q, const float* __restrict__ k2,
    const float* __restrict__ v2, float* __restrict__ out)
{
    int n = blockIdx.x * 4 + (threadIdx.x >> 5);
    int lane = threadIdx.x & 31;
    const float* kp = k2 + (size_t)n * 2048;
    const float* vp = v2 + (size_t)n * 2048;
    float qr[16];
    const float* qp = q + (size_t)n * 512 + lane * 16;
#pragma unroll
    for (int p = 0; p < 16; p++) qr[p] = qp[p];
    float m = -INFINITY;
    for (int s = 0; s < 128; s++) {
        float d = 0.f;
#pragma unroll
        for (int p = 0; p < 16; p++) d = fmaf(qr[p], kp[s * 16 + p], d);
        m = fmaxf(m, d);
    }
    float sum = 0.f;
    float V[16];
#pragma unroll
    for (int p = 0; p < 16; p++) V[p] = 0.f;
    for (int s = 0; s < 128; s++) {
        float d = 0.f;
#pragma unroll
        for (int p = 0; p < 16; p++) d = fmaf(qr[p], kp[s * 16 + p], d);
        float w = expf((d - m) * 0.25f);
        sum += w;
#pragma unroll
        for (int p = 0; p < 16; p++) V[p] = fmaf(w, vp[s * 16 + p], V[p]);
    }
    float inv = 1.f / sum;
    float* op = out + (size_t)n * 512 + lane * 16;
#pragma unroll
    for (int p = 0; p < 16; p++) op[p] = V[p] * inv;
}

// ---------------- layernorm over 2048 -------------------------------------------
__global__ __launch_bounds__(256) void ln_kernel(
    const float* __restrict__ in, const float* __restrict__ g,
    const float* __restrict__ b, float* __restrict__ out)
{
    int n = blockIdx.x;
    int tid = threadIdx.x;
    __shared__ float red[256];
    const float* x = in + (size_t)n * 2048;
    float s = 0.f;
    for (int i = tid; i < 2048; i += 256) s += x[i];
    red[tid] = s; __syncthreads();
    for (int o = 128; o > 0; o >>= 1) { if (tid < o) red[tid] += red[tid + o]; __syncthreads(); }
    float mean = red[0] * (1.f / 2048.f);
    __syncthreads();
    float vs = 0.f;
    for (int i = tid; i < 2048; i += 256) { float d = x[i] - mean; vs += d * d; }
    red[tid] = vs; __syncthreads();
    for (int o = 128; o > 0; o >>= 1) { if (tid < o) red[tid] += red[tid + o]; __syncthreads(); }
    float var = red[0] * (1.f / 2048.f);
    float inv = rsqrtf(var + 1e-5f);
    float* op = out + (size_t)n * 2048;
    for (int i = tid; i < 2048; i += 256) op[i] = (x[i] - mean) * inv * g[i] + b[i];
}

// ---------------- launch --------------------------------------------------------
extern "C" void kernel_launch(void* const* d_in, const int* in_sizes, int n_in,
                              void* d_out, int out_size)
{
    (void)in_sizes; (void)n_in; (void)out_size;
    const float* x     = (const float*)d_in[0];
    const float* aqw   = (const float*)d_in[1];
    const float* aqb   = (const float*)d_in[2];
    const float* akw   = (const float*)d_in[3];
    const float* akb   = (const float*)d_in[4];
    const float* avw   = (const float*)d_in[5];
    const float* avb   = (const float*)d_in[6];
    const float* aow   = (const float*)d_in[7];
    const float* aob   = (const float*)d_in[8];
    const float* encw  = (const float*)d_in[9];
    const float* encb  = (const float*)d_in[10];
    const float* f1qw  = (const float*)d_in[11];
    const float* f1qb  = (const float*)d_in[12];
    const float* f1kw  = (const float*)d_in[13];
    const float* f1kb  = (const float*)d_in[14];
    const float* f1vw  = (const float*)d_in[15];
    const float* f1vb  = (const float*)d_in[16];
    const float* f1ow  = (const float*)d_in[17];
    const float* f1ob  = (const float*)d_in[18];
    const float* f2qw  = (const float*)d_in[19];
    const float* f2qb  = (const float*)d_in[20];
    const float* f2kw  = (const float*)d_in[21];
    const float* f2kb  = (const float*)d_in[22];
    const float* f2vw  = (const float*)d_in[23];
    const float* f2vb  = (const float*)d_in[24];
    const float* f2ow  = (const float*)d_in[25];
    const float* f2ob  = (const float*)d_in[26];
    const float* lng   = (const float*)d_in[27];
    const float* lnb   = (const float*)d_in[28];

    float* out  = (float*)d_out;
    float* Aout = out + (size_t)NROWS * 512;

    float* b512; float* b2048; float* wt;
    cudaGetSymbolAddress((void**)&b512,  g_buf512);
    cudaGetSymbolAddress((void**)&b2048, g_buf2048);
    cudaGetSymbolAddress((void**)&wt,    g_wt);
    const size_t S = (size_t)NROWS * 512;
    const size_t T = (size_t)NROWS * 2048;
    float* qb   = b512;
    float* kb   = b512 + S;
    float* vb   = b512 + 2 * S;
    float* att  = b512 + 3 * S;
    float* zb   = b512 + 4 * S;
    float* y2   = b512 + 5 * S;
    float* q1   = b2048;
    float* Vf1  = b2048 + T;
    float* t1   = b2048 + 2 * T;
    float* u    = b2048 + 3 * T;

    cudaFuncSetAttribute(mm_gemm_kernel<0>, cudaFuncAttributeMaxDynamicSharedMemorySize, MM_SMEM);
    cudaFuncSetAttribute(mm_gemm_kernel<1>, cudaFuncAttributeMaxDynamicSharedMemorySize, MM_SMEM);
    cudaFuncSetAttribute(mm_gemm_kernel<2>, cudaFuncAttributeMaxDynamicSharedMemorySize, MM_SMEM);
    cudaFuncSetAttribute(mm_gemm_kernel<3>, cudaFuncAttributeMaxDynamicSharedMemorySize, MM_SMEM);
    cudaFuncSetAttribute(mm_gemm_kernel<4>, cudaFuncAttributeMaxDynamicSharedMemorySize, MM_SMEM);

    dim3 blk(256);
    dim3 tb(32, 8);
    dim3 tg512(4, (NROWS + 127) / 128);
    dim3 tg2048(16, (NROWS + 127) / 128);
    dim3 g64(8, (NROWS + 63) / 64);

    // ---- weight transposes ([K,N] -> [N,K]) ----
    transpose_kernel<<<dim3(16, 16), tb>>>(avw,  wt + OFF_AV,  512,  512);
    transpose_kernel<<<dim3(16, 16), tb>>>(aow,  wt + OFF_AO,  512,  512);
    transpose_kernel<<<dim3(16, 16), tb>>>(encw, wt + OFF_ENC, 512,  512);
    transpose_kernel<<<dim3(64, 16), tb>>>(f1qw, wt + OFF_F1Q, 512,  2048);
    transpose_kernel<<<dim3(16, 16), tb>>>(f1kw, wt + OFF_F1K, 512,  512);
    transpose_kernel<<<dim3(16, 16), tb>>>(f1vw, wt + OFF_F1V, 512,  512);
    transpose_kernel<<<dim3(64, 64), tb>>>(f1ow, wt + OFF_F1O, 2048, 2048);
    transpose_kernel<<<dim3(16, 64), tb>>>(f2qw, wt + OFF_F2Q, 2048, 512);
    transpose_kernel<<<dim3(64, 64), tb>>>(f2kw, wt + OFF_F2K, 2048, 2048);
    transpose_kernel<<<dim3(64, 64), tb>>>(f2vw, wt + OFF_F2V, 2048, 2048);
    transpose_kernel<<<dim3(16, 16), tb>>>(f2ow, wt + OFF_F2O, 512,  512);

    // ---- graph attention (q,k,scores exact fp64: feeds top-k) ----
    gemm64_kernel<<<g64, blk>>>(x, aqw, aqb, qb, NROWS, 512, 512, 1);
    gemm64_kernel<<<g64, blk>>>(x, akw, akb, kb, NROWS, 512, 512, 0);
    mm_gemm_kernel<1><<<tg512, blk, MM_SMEM>>>(x, wt + OFF_AV, avb, nullptr, vb, NROWS, 512, 512);
    scores_kernel<<<dim3(11, 11, 512), blk>>>(qb, kb, Aout);
    topk_softmax_kernel<<<20544, blk>>>(Aout);
    av_kernel<<<dim3(1, 6, 512), blk>>>(Aout, vb, att);
    mm_gemm_kernel<2><<<tg512, blk, MM_SMEM>>>(att, wt + OFF_AO, aob, x, zb, NROWS, 512, 512);
    mm_gemm_kernel<0><<<tg512, blk, MM_SMEM>>>(zb, wt + OFF_ENC, encb, nullptr, y2, NROWS, 512, 512);

    // ---- ff1 pwattn ----
    mm_gemm_kernel<1><<<tg2048, blk, MM_SMEM>>>(y2, wt + OFF_F1Q, f1qb, nullptr, q1, NROWS, 2048, 512);
    mm_gemm_kernel<0><<<tg512, blk, MM_SMEM>>>(y2, wt + OFF_F1K, f1kb, nullptr, qb, NROWS, 512, 512);
    mm_gemm_kernel<1><<<tg512, blk, MM_SMEM>>>(y2, wt + OFF_F1V, f1vb, nullptr, kb, NROWS, 512, 512);
    pwattn1_kernel<<<NROWS, 128>>>(q1, qb, kb, Vf1);
    mm_gemm_kernel<3><<<tg2048, blk, MM_SMEM>>>(Vf1, wt + OFF_F1O, f1ob, q1, t1, NROWS, 2048, 2048);
    ln_kernel<<<NROWS, blk>>>(t1, lng, lnb, u);

    // ---- ff2 pwattn ----
    mm_gemm_kernel<1><<<tg512, blk, MM_SMEM>>>(u, wt + OFF_F2Q, f2qb, nullptr, vb, NROWS, 512, 2048);
    mm_gemm_kernel<0><<<tg2048, blk, MM_SMEM>>>(u, wt + OFF_F2K, f2kb, nullptr, q1, NROWS, 2048, 2048);
    mm_gemm_kernel<1><<<tg2048, blk, MM_SMEM>>>(u, wt + OFF_F2V, f2vb, nullptr, Vf1, NROWS, 2048, 2048);
    pwattn2_kernel<<<NROWS / 4, 128>>>(vb, q1, Vf1, att);
    mm_gemm_kernel<4><<<tg512, blk, MM_SMEM>>>(att, wt + OFF_F2O, f2ob, vb, out, NROWS, 512, 512);
}

// round 7
// speedup vs baseline: 1.2775x; 1.1981x over previous
#include <cuda_runtime.h>
#include <cuda_bf16.h>
#include <math.h>
#include <stdint.h>

#define NROWS 20544     // B*L = 64*321
#define LL 321
#define DD 512
#define HH 8
#define EE 64
#define NTOPK 10

// ---------------- scratch (allocation-free: __device__ globals) ----------------
__device__ float    g_buf512[6ULL * NROWS * 512];    // f32: qb,kb,vb,k1,v1,qu2
__device__ float    g_buf2048[4ULL * NROWS * 2048];  // f32: q1/k2, t1, v2, spare
__device__ uint32_t g_sp_small[4ULL * NROWS * 512];  // split: x/att2, att, zb, y2
__device__ uint32_t g_sp_big[2ULL * NROWS * 2048];   // split: Vf1, u
__device__ uint32_t g_wt[16252928];                  // split transposed weights [N,K]

#define OFF_AV   0u
#define OFF_AO   262144u
#define OFF_ENC  524288u
#define OFF_F1Q  786432u
#define OFF_F1K  1835008u
#define OFF_F1V  2097152u
#define OFF_F1O  2359296u
#define OFF_F2Q  6553600u
#define OFF_F2K  7602176u
#define OFF_F2V  11796480u
#define OFF_F2O  15990784u

// ---------------- bf16 split helpers -------------------------------------------
__device__ __forceinline__ uint32_t fsplit(float x) {
    __nv_bfloat16 h = __float2bfloat16(x);
    float hf = __bfloat162float(h);
    __nv_bfloat16 l = __float2bfloat16(x - hf);
    return (uint32_t)__bfloat16_as_ushort(h) | ((uint32_t)__bfloat16_as_ushort(l) << 16);
}
// from two packed elements (k, k+1) produce hi-pair and lo-pair regs
__device__ __forceinline__ void ld_pair(const uint32_t* s, uint32_t& hi, uint32_t& lo) {
    uint2 p = *(const uint2*)s;
    hi = __byte_perm(p.x, p.y, 0x5410);
    lo = __byte_perm(p.x, p.y, 0x7632);
}

// ============================ weight transpose + split =========================
// src [K,N] f32 row-major -> dst [N,K] packed-split u32 row-major
__global__ void transpose_split_kernel(const float* __restrict__ src, uint32_t* __restrict__ dst,
                                       int K, int N)
{
    __shared__ float t[32][33];
    int bx = blockIdx.x * 32, by = blockIdx.y * 32;
    int txi = threadIdx.x, tyi = threadIdx.y;
#pragma unroll
    for (int j = 0; j < 32; j += 8)
        t[tyi + j][txi] = src[(size_t)(by + tyi + j) * N + bx + txi];
    __syncthreads();
#pragma unroll
    for (int j = 0; j < 32; j += 8)
        dst[(size_t)(bx + tyi + j) * K + by + txi] = fsplit(t[txi][tyi + j]);
}

// f32 -> packed split u32, elementwise
__global__ void convert_kernel(const float* __restrict__ in, uint32_t* __restrict__ outp, int n)
{
    for (int i = blockIdx.x * 256 + threadIdx.x; i < n; i += gridDim.x * 256)
        outp[i] = fsplit(in[i]);
}

// ================= bf16x3 mma.sync GEMM (fp32-class accuracy) ==================
// C = act(A[M,K] @ Bt[N,K]^T + bias (+res)); A,Bt in packed-split u32; K%32==0.
// EP: 0=bias, 1=bias+relu, 2=bias+res+leaky(0.5), 3=bias+res+elu, 4=bias+res
// OM: 0 -> f32 out, 1 -> packed-split u32 out
#define MM_PITCH 40                       // u32 per smem row (32 + 8 pad)
#define MM_HALF  (128 * MM_PITCH)         // u32 per A (or B) part
#define MM_STAGE (2 * MM_HALF)            // u32 per stage
#define MM_SMEM  (2 * MM_STAGE * 4)       // bytes (81920)

__device__ __forceinline__ void mm_load_stage(
    const uint32_t* __restrict__ A, const uint32_t* __restrict__ Bt,
    int bm, int bn, int M, int K, int k0, uint32_t* st, int tid)
{
    uint32_t a_s, b_s;
    asm("{ .reg .u64 t; cvta.to.shared.u64 t, %1; cvt.u32.u64 %0, t; }" : "=r"(a_s) : "l"(st));
    b_s = a_s + MM_HALF * 4;
#pragma unroll
    for (int j = 0; j < 4; j++) {
        int idx = tid + j * 256;
        int r = idx >> 3, c = idx & 7;
        uint32_t doff = (uint32_t)(r * MM_PITCH + c * 4) * 4;
        int grow = bm + r;
        const uint32_t* srcA = A + (size_t)(grow < M ? grow : 0) * K + k0 + c * 4;
        int szA = (grow < M) ? 16 : 0;
        asm volatile("cp.async.ca.shared.global [%0], [%1], 16, %2;"
                     :: "r"(a_s + doff), "l"(srcA), "r"(szA));
        const uint32_t* srcB = Bt + (size_t)(bn + r) * K + k0 + c * 4;
        asm volatile("cp.async.ca.shared.global [%0], [%1], 16;"
                     :: "r"(b_s + doff), "l"(srcB));
    }
    asm volatile("cp.async.commit_group;" ::: "memory");
}

#define MMA_BF16(acc, a0, a1, a2, a3, b0, b1) \
    asm volatile( \
        "mma.sync.aligned.m16n8k16.row.col.f32.bf16.bf16.f32 " \
        "{%0,%1,%2,%3}, {%4,%5,%6,%7}, {%8,%9}, {%0,%1,%2,%3};" \
        : "+f"((acc)[0]), "+f"((acc)[1]), "+f"((acc)[2]), "+f"((acc)[3]) \
        : "r"(a0), "r"(a1), "r"(a2), "r"(a3), "r"(b0), "r"(b1))

template<int EP, int OM>
__global__ __launch_bounds__(256)
void mm_gemm_kernel(const uint32_t* __restrict__ A, const uint32_t* __restrict__ Bt,
                    const float* __restrict__ bias, const float* __restrict__ res,
                    void* __restrict__ Cv, int M, int N, int K)
{
    extern __shared__ uint32_t sm[];
    const int tid = threadIdx.x;
    const int wid = tid >> 5, lane = tid & 31;
    const int wm = wid >> 2, wn = wid & 3;     // 2 x 4 warps
    const int g = lane >> 2, t = lane & 3;
    const int bm = blockIdx.y * 128, bn = blockIdx.x * 128;

    float acc[4][4][4];
#pragma unroll
    for (int i = 0; i < 4; i++)
#pragma unroll
        for (int j = 0; j < 4; j++)
#pragma unroll
            for (int q = 0; q < 4; q++) acc[i][j][q] = 0.f;

    const int nc = K >> 5;
    mm_load_stage(A, Bt, bm, bn, M, K, 0, sm, tid);

    for (int c = 0; c < nc; c++) {
        if (c + 1 < nc)
            mm_load_stage(A, Bt, bm, bn, M, K, (c + 1) * 32, sm + ((c + 1) & 1) * MM_STAGE, tid);
        if (c + 1 < nc) asm volatile("cp.async.wait_group 1;" ::: "memory");
        else            asm volatile("cp.async.wait_group 0;" ::: "memory");
        __syncthreads();

        const uint32_t* As = sm + (c & 1) * MM_STAGE;
        const uint32_t* Bs = As + MM_HALF;
#pragma unroll
        for (int ks = 0; ks < 2; ks++) {
            uint32_t ah[4][4], al[4][4], bh[4][2], bl[4][2];
#pragma unroll
            for (int mt = 0; mt < 4; mt++) {
                const uint32_t* base = As + (wm * 64 + mt * 16 + g) * MM_PITCH + ks * 16 + 2 * t;
                ld_pair(base,                  ah[mt][0], al[mt][0]);
                ld_pair(base + 8 * MM_PITCH,   ah[mt][1], al[mt][1]);
                ld_pair(base + 8,              ah[mt][2], al[mt][2]);
                ld_pair(base + 8 * MM_PITCH + 8, ah[mt][3], al[mt][3]);
            }
#pragma unroll
            for (int nt = 0; nt < 4; nt++) {
                const uint32_t* base = Bs + (wn * 32 + nt * 8 + g) * MM_PITCH + ks * 16 + 2 * t;
                ld_pair(base,     bh[nt][0], bl[nt][0]);
                ld_pair(base + 8, bh[nt][1], bl[nt][1]);
            }
#pragma unroll
            for (int mt = 0; mt < 4; mt++)
#pragma unroll
                for (int nt = 0; nt < 4; nt++) {
                    MMA_BF16(acc[mt][nt], ah[mt][0], ah[mt][1], ah[mt][2], ah[mt][3],
                             bl[nt][0], bl[nt][1]);
                    MMA_BF16(acc[mt][nt], al[mt][0], al[mt][1], al[mt][2], al[mt][3],
                             bh[nt][0], bh[nt][1]);
                    MMA_BF16(acc[mt][nt], ah[mt][0], ah[mt][1], ah[mt][2], ah[mt][3],
                             bh[nt][0], bh[nt][1]);
                }
        }
        __syncthreads();
    }

    // epilogue: d0,d1 -> (row g, cols t*2,t*2+1); d2,d3 -> row g+8
    float* Cf = (float*)Cv;
    uint32_t* Cs = (uint32_t*)Cv;
#pragma unroll
    for (int mt = 0; mt < 4; mt++) {
#pragma unroll
        for (int half = 0; half < 2; half++) {
            int row = bm + wm * 64 + mt * 16 + g + half * 8;
            if (row >= M) continue;
#pragma unroll
            for (int nt = 0; nt < 4; nt++) {
                int col = bn + wn * 32 + nt * 8 + t * 2;
                float v0 = acc[mt][nt][half * 2 + 0] + bias[col];
                float v1 = acc[mt][nt][half * 2 + 1] + bias[col + 1];
                if (EP >= 2) {
                    v0 += res[(size_t)row * N + col];
                    v1 += res[(size_t)row * N + col + 1];
                }
                if (EP == 1) { v0 = fmaxf(v0, 0.f); v1 = fmaxf(v1, 0.f); }
                if (EP == 2) { v0 = (v0 > 0.f) ? v0 : 0.5f * v0; v1 = (v1 > 0.f) ? v1 : 0.5f * v1; }
                if (EP == 3) { v0 = (v0 > 0.f) ? v0 : expm1f(v0); v1 = (v1 > 0.f) ? v1 : expm1f(v1); }
                if (OM == 0) {
                    *(float2*)(Cf + (size_t)row * N + col) = make_float2(v0, v1);
                } else {
                    uint2 o = make_uint2(fsplit(v0), fsplit(v1));
                    *(uint2*)(Cs + (size_t)row * N + col) = o;
                }
            }
        }
    }
}

// ---------------- fp64-accumulate GEMM (exact), q/k feeding top-k ---------------
__global__ __launch_bounds__(256) void gemm64_kernel(
    const float* __restrict__ A, const float* __restrict__ B,
    const float* __restrict__ bias, float* __restrict__ C,
    int M, int N, int K, int relu)
{
    __shared__ double As[16][65];
    __shared__ double Bs[16][65];
    const int tid = threadIdx.x;
    const int bm = blockIdx.y * 64;
    const int bn = blockIdx.x * 64;
    const int ty = tid >> 4, tx = tid & 15;

    double acc[4][4];
#pragma unroll
    for (int i = 0; i < 4; i++)
#pragma unroll
        for (int j = 0; j < 4; j++) acc[i][j] = 0.0;

    const int ar = tid >> 2;
    const int ac = (tid & 3) << 2;
    const int br = tid >> 4;
    const int bc = (tid & 15) << 2;

    for (int k0 = 0; k0 < K; k0 += 16) {
        {
            int grow = bm + ar;
            float4 v = make_float4(0.f, 0.f, 0.f, 0.f);
            if (grow < M) v = *(const float4*)(A + (size_t)grow * K + k0 + ac);
            As[ac + 0][ar] = (double)v.x; As[ac + 1][ar] = (double)v.y;
            As[ac + 2][ar] = (double)v.z; As[ac + 3][ar] = (double)v.w;
        }
        {
            float4 v = *(const float4*)(B + (size_t)(k0 + br) * N + bn + bc);
            Bs[br][bc + 0] = (double)v.x; Bs[br][bc + 1] = (double)v.y;
            Bs[br][bc + 2] = (double)v.z; Bs[br][bc + 3] = (double)v.w;
        }
        __syncthreads();
#pragma unroll
        for (int kk = 0; kk < 16; kk++) {
            double a[4], b[4];
#pragma unroll
            for (int i = 0; i < 4; i++) a[i] = As[kk][ty * 4 + i];
#pragma unroll
            for (int j = 0; j < 4; j++) b[j] = Bs[kk][tx * 4 + j];
#pragma unroll
            for (int i = 0; i < 4; i++)
#pragma unroll
                for (int j = 0; j < 4; j++) acc[i][j] = fma(a[i], b[j], acc[i][j]);
        }
        __syncthreads();
    }

#pragma unroll
    for (int i = 0; i < 4; i++) {
        int row = bm + ty * 4 + i;
        if (row < M) {
#pragma unroll
            for (int j = 0; j < 4; j++) {
                int col = bn + tx * 4 + j;
                double v = acc[i][j] + (double)bias[col];
                if (relu && v < 0.0) v = 0.0;
                C[(size_t)row * N + col] = (float)v;
            }
        }
    }
}

// ---------------- batched scores (fp64 accumulate, exact) -----------------------
__global__ __launch_bounds__(256) void scores_kernel(
    const float* __restrict__ q, const float* __restrict__ k, float* __restrict__ out)
{
    int bh = blockIdx.z;
    int b = bh >> 3, h = bh & 7;
    int l0 = blockIdx.y * 32, s0 = blockIdx.x * 32;
    __shared__ double Qs[32][65];
    __shared__ double Ks[32][65];
    int tid = threadIdx.x;
    int r = tid >> 3;
    int c = (tid & 7) * 8;
    {
        int l = l0 + r;
        if (l < LL) {
            const float* src = q + ((size_t)(b * LL + l)) * DD + h * EE + c;
            float4 v0 = *(const float4*)src;
            float4 v1 = *(const float4*)(src + 4);
            Qs[r][c+0]=(double)v0.x; Qs[r][c+1]=(double)v0.y; Qs[r][c+2]=(double)v0.z; Qs[r][c+3]=(double)v0.w;
            Qs[r][c+4]=(double)v1.x; Qs[r][c+5]=(double)v1.y; Qs[r][c+6]=(double)v1.z; Qs[r][c+7]=(double)v1.w;
        } else {
#pragma unroll
            for (int t = 0; t < 8; t++) Qs[r][c+t] = 0.0;
        }
        int s = s0 + r;
        if (s < LL) {
            const float* src = k + ((size_t)(b * LL + s)) * DD + h * EE + c;
            float4 v0 = *(const float4*)src;
            float4 v1 = *(const float4*)(src + 4);
            Ks[r][c+0]=(double)v0.x; Ks[r][c+1]=(double)v0.y; Ks[r][c+2]=(double)v0.z; Ks[r][c+3]=(double)v0.w;
            Ks[r][c+4]=(double)v1.x; Ks[r][c+5]=(double)v1.y; Ks[r][c+6]=(double)v1.z; Ks[r][c+7]=(double)v1.w;
        } else {
#pragma unroll
            for (int t = 0; t < 8; t++) Ks[r][c+t] = 0.0;
        }
    }
    __syncthreads();
    int ty = tid >> 4, tx = tid & 15;
    double acc[2][2] = {{0.0,0.0},{0.0,0.0}};
#pragma unroll 4
    for (int kk = 0; kk < EE; kk++) {
        double a0 = Qs[ty*2+0][kk], a1 = Qs[ty*2+1][kk];
        double b0 = Ks[tx*2+0][kk], b1 = Ks[tx*2+1][kk];
        acc[0][0] = fma(a0, b0, acc[0][0]);
        acc[0][1] = fma(a0, b1, acc[0][1]);
        acc[1][0] = fma(a1, b0, acc[1][0]);
        acc[1][1] = fma(a1, b1, acc[1][1]);
    }
    size_t base = (size_t)bh * LL * LL;
#pragma unroll
    for (int i = 0; i < 2; i++) {
        int l = l0 + ty * 2 + i;
        if (l < LL) {
#pragma unroll
            for (int j = 0; j < 2; j++) {
                int s = s0 + tx * 2 + j;
                if (s < LL) out[base + (size_t)l * LL + s] = (float)acc[i][j];
            }
        }
    }
}

// ---------------- top-k mask + softmax, in place on scores ----------------
__global__ __launch_bounds__(256) void topk_softmax_kernel(float* __restrict__ A)
{
    const int lane = threadIdx.x & 31;
    const int wslot = threadIdx.x >> 5;
    const size_t row = (size_t)blockIdx.x * 8 + wslot;
    __shared__ float sm[8][352];
    float* s = sm[wslot];
    float* rp = A + row * LL;

    float r[11];
#pragma unroll
    for (int j = 0; j < 11; j++) {
        int idx = lane + j * 32;
        float v = (idx < LL) ? rp[idx] : -INFINITY;
        r[j] = v;
        s[idx] = v;
    }
    __syncwarp();

    float kth = 0.f, mmax = 0.f;
    for (int it = 0; it < NTOPK; it++) {
        float lm = -INFINITY;
#pragma unroll
        for (int j = 0; j < 11; j++) lm = fmaxf(lm, s[lane + j * 32]);
        float gm = lm;
#pragma unroll
        for (int o = 16; o > 0; o >>= 1) gm = fmaxf(gm, __shfl_xor_sync(0xffffffffu, gm, o));
        if (it == 0) mmax = gm;
        kth = gm;
        int li = 0x7fffffff;
#pragma unroll
        for (int j = 10; j >= 0; j--) {
            int idx = lane + j * 32;
            if (s[idx] == gm) li = idx;
        }
        int gi = li;
#pragma unroll
        for (int o = 16; o > 0; o >>= 1) gi = min(gi, __shfl_xor_sync(0xffffffffu, gi, o));
        if (li == gi) s[li] = -INFINITY;
        __syncwarp();
    }

    const float scale = 0.125f;
    float e[11];
    float sum = 0.f;
#pragma unroll
    for (int j = 0; j < 11; j++) {
        int idx = lane + j * 32;
        float v = r[j];
        float t = (idx < LL && v >= kth) ? expf((v - mmax) * scale) : 0.f;
        e[j] = t;
        sum += t;
    }
#pragma unroll
    for (int o = 16; o > 0; o >>= 1) sum += __shfl_xor_sync(0xffffffffu, sum, o);
    float inv = 1.f / sum;
#pragma unroll
    for (int j = 0; j < 11; j++) {
        int idx = lane + j * 32;
        if (idx < LL) rp[idx] = e[j] * inv;
    }
}

// ---------------- A @ V -> split output -----------------------------------------
__global__ __launch_bounds__(256) void av_kernel(
    const float* __restrict__ A, const float* __restrict__ v, uint32_t* __restrict__ out)
{
    int bh = blockIdx.z;
    int b = bh >> 3, h = bh & 7;
    int l0 = blockIdx.y * 64;
    __shared__ float As2[64][17];
    __shared__ float Vs[16][65];
    int tid = threadIdx.x;
    int ty = tid >> 4, tx = tid & 15;
    float acc[4][4];
#pragma unroll
    for (int i = 0; i < 4; i++)
#pragma unroll
        for (int j = 0; j < 4; j++) acc[i][j] = 0.f;

    const int ar = tid >> 2, ac = (tid & 3) * 4;
    const int vr = tid >> 4, vc = (tid & 15) * 4;
    size_t abase = (size_t)bh * LL * LL;

    for (int s0 = 0; s0 < LL; s0 += 16) {
        int l = l0 + ar;
#pragma unroll
        for (int cc = 0; cc < 4; cc++) {
            int sidx = s0 + ac + cc;
            As2[ar][ac + cc] = (l < LL && sidx < LL) ? A[abase + (size_t)l * LL + sidx] : 0.f;
        }
        int sv = s0 + vr;
        if (sv < LL) {
            float4 t = *(const float4*)(v + ((size_t)(b * LL + sv)) * DD + h * EE + vc);
            Vs[vr][vc+0]=t.x; Vs[vr][vc+1]=t.y; Vs[vr][vc+2]=t.z; Vs[vr][vc+3]=t.w;
        } else {
#pragma unroll
            for (int t = 0; t < 4; t++) Vs[vr][vc+t] = 0.f;
        }
        __syncthreads();
#pragma unroll
        for (int kk = 0; kk < 16; kk++) {
            float a[4], bb2[4];
#pragma unroll
            for (int i = 0; i < 4; i++) a[i] = As2[ty*4+i][kk];
#pragma unroll
            for (int j = 0; j < 4; j++) bb2[j] = Vs[kk][tx*4+j];
#pragma unroll
            for (int i = 0; i < 4; i++)
#pragma unroll
                for (int j = 0; j < 4; j++) acc[i][j] = fmaf(a[i], bb2[j], acc[i][j]);
        }
        __syncthreads();
    }
#pragma unroll
    for (int i = 0; i < 4; i++) {
        int l = l0 + ty * 4 + i;
        if (l < LL) {
#pragma unroll
            for (int j = 0; j < 4; j++) {
                int e = tx * 4 + j;
                out[((size_t)(b * LL + l)) * DD + h * EE + e] = fsplit(acc[i][j]);
            }
        }
    }
}

// ---------------- pwattn1: split output -----------------------------------------
__global__ __launch_bounds__(128) void pwattn1_kernel(
    const float* __restrict__ q, const float* __restrict__ k,
    const float* __restrict__ v, uint32_t* __restrict__ out)
{
    int n = blockIdx.x;
    int l = threadIdx.x;
    __shared__ float sk[512];
    __shared__ float sv[512];
    int t4 = l * 4;
    *(float4*)&sk[t4] = *(const float4*)(k + (size_t)n * 512 + t4);
    *(float4*)&sv[t4] = *(const float4*)(v + (size_t)n * 512 + t4);
    __syncthreads();
    float qr[16];
    const float* qp = q + (size_t)n * 2048 + l * 16;
#pragma unroll
    for (int p = 0; p < 16; p++) qr[p] = qp[p];
    float sc[32];
    float m = -INFINITY;
#pragma unroll
    for (int s = 0; s < 32; s++) {
        float d = 0.f;
#pragma unroll
        for (int p = 0; p < 16; p++) d = fmaf(qr[p], sk[s * 16 + p], d);
        sc[s] = d;
        m = fmaxf(m, d);
    }
    float sum = 0.f;
    float V[16];
#pragma unroll
    for (int p = 0; p < 16; p++) V[p] = 0.f;
#pragma unroll
    for (int s = 0; s < 32; s++) {
        float w = expf((sc[s] - m) * 0.25f);
        sum += w;
#pragma unroll
        for (int p = 0; p < 16; p++) V[p] = fmaf(w, sv[s * 16 + p], V[p]);
    }
    float inv = 1.f / sum;
    uint32_t* op = out + (size_t)n * 2048 + l * 16;
#pragma unroll
    for (int p = 0; p < 16; p++) op[p] = fsplit(V[p] * inv);
}

// ---------------- pwattn2: split output -----------------------------------------
__global__ __launch_bounds__(128) void pwattn2_kernel(
    const float* __restrict__ q, const float* __restrict__ k2,
    const float* __restrict__ v2, uint32_t* __restrict__ out)
{
    int n = blockIdx.x * 4 + (threadIdx.x >> 5);
    int lane = threadIdx.x & 31;
    const float* kp = k2 + (size_t)n * 2048;
    const float* vp = v2 + (size_t)n * 2048;
    float qr[16];
    const float* qp = q + (size_t)n * 512 + lane * 16;
#pragma unroll
    for (int p = 0; p < 16; p++) qr[p] = qp[p];
    float m = -INFINITY;
    for (int s = 0; s < 128; s++) {
        float d = 0.f;
#pragma unroll
        for (int p = 0; p < 16; p++) d = fmaf(qr[p], kp[s * 16 + p], d);
        m = fmaxf(m, d);
    }
    float sum = 0.f;
    float V[16];
#pragma unroll
    for (int p = 0; p < 16; p++) V[p] = 0.f;
    for (int s = 0; s < 128; s++) {
        float d = 0.f;
#pragma unroll
        for (int p = 0; p < 16; p++) d = fmaf(qr[p], kp[s * 16 + p], d);
        float w = expf((d - m) * 0.25f);
        sum += w;
#pragma unroll
        for (int p = 0; p < 16; p++) V[p] = fmaf(w, vp[s * 16 + p], V[p]);
    }
    float inv = 1.f / sum;
    uint32_t* op = out + (size_t)n * 512 + lane * 16;
#pragma unroll
    for (int p = 0; p < 16; p++) op[p] = fsplit(V[p] * inv);
}

// ---------------- layernorm over 2048 -> split output ---------------------------
__global__ __launch_bounds__(256) void ln_kernel(
    const float* __restrict__ in, const float* __restrict__ g,
    const float* __restrict__ b, uint32_t* __restrict__ out)
{
    int n = blockIdx.x;
    int tid = threadIdx.x;
    __shared__ float red[256];
    const float* x = in + (size_t)n * 2048;
    float s = 0.f;
    for (int i = tid; i < 2048; i += 256) s += x[i];
    red[tid] = s; __syncthreads();
    for (int o = 128; o > 0; o >>= 1) { if (tid < o) red[tid] += red[tid + o]; __syncthreads(); }
    float mean = red[0] * (1.f / 2048.f);
    __syncthreads();
    float vs = 0.f;
    for (int i = tid; i < 2048; i += 256) { float d = x[i] - mean; vs += d * d; }
    red[tid] = vs; __syncthreads();
    for (int o = 128; o > 0; o >>= 1) { if (tid < o) red[tid] += red[tid + o]; __syncthreads(); }
    float var = red[0] * (1.f / 2048.f);
    float inv = rsqrtf(var + 1e-5f);
    uint32_t* op = out + (size_t)n * 2048;
    for (int i = tid; i < 2048; i += 256) op[i] = fsplit((x[i] - mean) * inv * g[i] + b[i]);
}

// ---------------- launch --------------------------------------------------------
extern "C" void kernel_launch(void* const* d_in, const int* in_sizes, int n_in,
                              void* d_out, int out_size)
{
    (void)in_sizes; (void)n_in; (void)out_size;
    const float* x     = (const float*)d_in[0];
    const float* aqw   = (const float*)d_in[1];
    const float* aqb   = (const float*)d_in[2];
    const float* akw   = (const float*)d_in[3];
    const float* akb   = (const float*)d_in[4];
    const float* avw   = (const float*)d_in[5];
    const float* avb   = (const float*)d_in[6];
    const float* aow   = (const float*)d_in[7];
    const float* aob   = (const float*)d_in[8];
    const float* encw  = (const float*)d_in[9];
    const float* encb  = (const float*)d_in[10];
    const float* f1qw  = (const float*)d_in[11];
    const float* f1qb  = (const float*)d_in[12];
    const float* f1kw  = (const float*)d_in[13];
    const float* f1kb  = (const float*)d_in[14];
    const float* f1vw  = (const float*)d_in[15];
    const float* f1vb  = (const float*)d_in[16];
    const float* f1ow  = (const float*)d_in[17];
    const float* f1ob  = (const float*)d_in[18];
    const float* f2qw  = (const float*)d_in[19];
    const float* f2qb  = (const float*)d_in[20];
    const float* f2kw  = (const float*)d_in[21];
    const float* f2kb  = (const float*)d_in[22];
    const float* f2vw  = (const float*)d_in[23];
    const float* f2vb  = (const float*)d_in[24];
    const float* f2ow  = (const float*)d_in[25];
    const float* f2ob  = (const float*)d_in[26];
    const float* lng   = (const float*)d_in[27];
    const float* lnb   = (const float*)d_in[28];

    float* out  = (float*)d_out;
    float* Aout = out + (size_t)NROWS * 512;

    float* b512; float* b2048; uint32_t* sps; uint32_t* spb; uint32_t* wt;
    cudaGetSymbolAddress((void**)&b512,  g_buf512);
    cudaGetSymbolAddress((void**)&b2048, g_buf2048);
    cudaGetSymbolAddress((void**)&sps,   g_sp_small);
    cudaGetSymbolAddress((void**)&spb,   g_sp_big);
    cudaGetSymbolAddress((void**)&wt,    g_wt);
    const size_t S = (size_t)NROWS * 512;
    const size_t T = (size_t)NROWS * 2048;
    float* qb   = b512;          // q (fp64 path)
    float* kb   = b512 + S;      // k (fp64 path)
    float* vb   = b512 + 2 * S;  // v
    float* k1   = b512 + 3 * S;
    float* v1   = b512 + 4 * S;
    float* qu2  = b512 + 5 * S;
    float* q1   = b2048;         // query1, later k2
    float* t1   = b2048 + T;
    float* v2   = b2048 + 2 * T;
    uint32_t* x_sp   = sps;          // later att2_sp
    uint32_t* att_sp = sps + S;
    uint32_t* zb_sp  = sps + 2 * S;
    uint32_t* y2_sp  = sps + 3 * S;
    uint32_t* Vf1_sp = spb;
    uint32_t* u_sp   = spb + T;

    cudaFuncSetAttribute(mm_gemm_kernel<0,0>, cudaFuncAttributeMaxDynamicSharedMemorySize, MM_SMEM);
    cudaFuncSetAttribute(mm_gemm_kernel<1,0>, cudaFuncAttributeMaxDynamicSharedMemorySize, MM_SMEM);
    cudaFuncSetAttribute(mm_gemm_kernel<3,0>, cudaFuncAttributeMaxDynamicSharedMemorySize, MM_SMEM);
    cudaFuncSetAttribute(mm_gemm_kernel<4,0>, cudaFuncAttributeMaxDynamicSharedMemorySize, MM_SMEM);
    cudaFuncSetAttribute(mm_gemm_kernel<2,1>, cudaFuncAttributeMaxDynamicSharedMemorySize, MM_SMEM);
    cudaFuncSetAttribute(mm_gemm_kernel<0,1>, cudaFuncAttributeMaxDynamicSharedMemorySize, MM_SMEM);

    dim3 blk(256);
    dim3 tb(32, 8);
    dim3 tg512(4, (NROWS + 127) / 128);
    dim3 tg2048(16, (NROWS + 127) / 128);
    dim3 g64(8, (NROWS + 63) / 64);

    // ---- weight transpose+split ([K,N] f32 -> [N,K] packed u32) ----
    transpose_split_kernel<<<dim3(16, 16), tb>>>(avw,  wt + OFF_AV,  512,  512);
    transpose_split_kernel<<<dim3(16, 16), tb>>>(aow,  wt + OFF_AO,  512,  512);
    transpose_split_kernel<<<dim3(16, 16), tb>>>(encw, wt + OFF_ENC, 512,  512);
    transpose_split_kernel<<<dim3(64, 16), tb>>>(f1qw, wt + OFF_F1Q, 512,  2048);
    transpose_split_kernel<<<dim3(16, 16), tb>>>(f1kw, wt + OFF_F1K, 512,  512);
    transpose_split_kernel<<<dim3(16, 16), tb>>>(f1vw, wt + OFF_F1V, 512,  512);
    transpose_split_kernel<<<dim3(64, 64), tb>>>(f1ow, wt + OFF_F1O, 2048, 2048);
    transpose_split_kernel<<<dim3(16, 64), tb>>>(f2qw, wt + OFF_F2Q, 2048, 512);
    transpose_split_kernel<<<dim3(64, 64), tb>>>(f2kw, wt + OFF_F2K, 2048, 2048);
    transpose_split_kernel<<<dim3(64, 64), tb>>>(f2vw, wt + OFF_F2V, 2048, 2048);
    transpose_split_kernel<<<dim3(16, 16), tb>>>(f2ow, wt + OFF_F2O, 512,  512);
    convert_kernel<<<4096, 256>>>(x, x_sp, (int)S);

    // ---- graph attention (q,k,scores exact fp64: feeds top-k) ----
    gemm64_kernel<<<g64, blk>>>(x, aqw, aqb, qb, NROWS, 512, 512, 1);
    gemm64_kernel<<<g64, blk>>>(x, akw, akb, kb, NROWS, 512, 512, 0);
    mm_gemm_kernel<1,0><<<tg512, blk, MM_SMEM>>>(x_sp, wt + OFF_AV, avb, nullptr, vb, NROWS, 512, 512);
    scores_kernel<<<dim3(11, 11, 512), blk>>>(qb, kb, Aout);
    topk_softmax_kernel<<<20544, blk>>>(Aout);
    av_kernel<<<dim3(1, 6, 512), blk>>>(Aout, vb, att_sp);
    mm_gemm_kernel<2,1><<<tg512, blk, MM_SMEM>>>(att_sp, wt + OFF_AO, aob, x, zb_sp, NROWS, 512, 512);
    mm_gemm_kernel<0,1><<<tg512, blk, MM_SMEM>>>(zb_sp, wt + OFF_ENC, encb, nullptr, y2_sp, NROWS, 512, 512);

    // ---- ff1 pwattn ----
    mm_gemm_kernel<1,0><<<tg2048, blk, MM_SMEM>>>(y2_sp, wt + OFF_F1Q, f1qb, nullptr, q1, NROWS, 2048, 512);
    mm_gemm_kernel<0,0><<<tg512, blk, MM_SMEM>>>(y2_sp, wt + OFF_F1K, f1kb, nullptr, k1, NROWS, 512, 512);
    mm_gemm_kernel<1,0><<<tg512, blk, MM_SMEM>>>(y2_sp, wt + OFF_F1V, f1vb, nullptr, v1, NROWS, 512, 512);
    pwattn1_kernel<<<NROWS, 128>>>(q1, k1, v1, Vf1_sp);
    mm_gemm_kernel<3,0><<<tg2048, blk, MM_SMEM>>>(Vf1_sp, wt + OFF_F1O, f1ob, q1, t1, NROWS, 2048, 2048);
    ln_kernel<<<NROWS, blk>>>(t1, lng, lnb, u_sp);

    // ---- ff2 pwattn ----
    mm_gemm_kernel<1,0><<<tg512, blk, MM_SMEM>>>(u_sp, wt + OFF_F2Q, f2qb, nullptr, qu2, NROWS, 512, 2048);
    mm_gemm_kernel<0,0><<<tg2048, blk, MM_SMEM>>>(u_sp, wt + OFF_F2K, f2kb, nullptr, q1, NROWS, 2048, 2048);
    mm_gemm_kernel<1,0><<<tg2048, blk, MM_SMEM>>>(u_sp, wt + OFF_F2V, f2vb, nullptr, v2, NROWS, 2048, 2048);
    pwattn2_kernel<<<NROWS / 4, 128>>>(qu2, q1, v2, x_sp);   // att2 -> reuse x_sp
    mm_gemm_kernel<4,0><<<tg512, blk, MM_SMEM>>>(x_sp, wt + OFF_F2O, f2ob, qu2, out, NROWS, 512, 512);
}

// round 8
// speedup vs baseline: 3.8369x; 3.0035x over previous
#include <cuda_runtime.h>
#include <cuda_bf16.h>
#include <math.h>
#include <stdint.h>

#define NROWS 20544     // B*L = 64*321
#define LL 321
#define DD 512
#define HH 8
#define EE 64
#define NTOPK 10

// ---------------- scratch (allocation-free: __device__ globals) ----------------
__device__ float    g_buf512[6ULL * NROWS * 512];    // f32: qb,kb,vb,k1,v1,qu2
__device__ float    g_buf2048[4ULL * NROWS * 2048];  // f32: q1/k2, t1, v2, spare
__device__ uint32_t g_sp_small[4ULL * NROWS * 512];  // split: x/att2, att, zb, y2
__device__ uint32_t g_sp_big[2ULL * NROWS * 2048];   // split: Vf1, u
__device__ uint32_t g_wt[16252928];                  // split transposed weights [N,K]

#define OFF_AV   0u
#define OFF_AO   262144u
#define OFF_ENC  524288u
#define OFF_F1Q  786432u
#define OFF_F1K  1835008u
#define OFF_F1V  2097152u
#define OFF_F1O  2359296u
#define OFF_F2Q  6553600u
#define OFF_F2K  7602176u
#define OFF_F2V  11796480u
#define OFF_F2O  15990784u

// ---------------- bf16 split helpers -------------------------------------------
__device__ __forceinline__ uint32_t fsplit(float x) {
    __nv_bfloat16 h = __float2bfloat16(x);
    float hf = __bfloat162float(h);
    __nv_bfloat16 l = __float2bfloat16(x - hf);
    return (uint32_t)__bfloat16_as_ushort(h) | ((uint32_t)__bfloat16_as_ushort(l) << 16);
}
__device__ __forceinline__ void ld_pair(const uint32_t* s, uint32_t& hi, uint32_t& lo) {
    uint2 p = *(const uint2*)s;
    hi = __byte_perm(p.x, p.y, 0x5410);
    lo = __byte_perm(p.x, p.y, 0x7632);
}

// ---------------- compensated fp32 MAC (TwoProdFMA + Kahan) --------------------
// error ~ K*2^-48: effectively exact for the top-k decision path.
__device__ __forceinline__ void kmac(float a, float b, float& s, float& c) {
    float p = __fmul_rn(a, b);
    float e = __fmaf_rn(a, b, -p);      // exact product low part
    float y = __fsub_rn(p, c);
    float t = __fadd_rn(s, y);
    c = __fsub_rn(__fsub_rn(t, s), y);
    c = __fsub_rn(c, e);                // fold product error into compensation
    s = t;
}
__device__ __forceinline__ float kfin(float s, float c) { return __fsub_rn(s, c); }

// ============================ weight transpose + split =========================
__global__ void transpose_split_kernel(const float* __restrict__ src, uint32_t* __restrict__ dst,
                                       int K, int N)
{
    __shared__ float t[32][33];
    int bx = blockIdx.x * 32, by = blockIdx.y * 32;
    int txi = threadIdx.x, tyi = threadIdx.y;
#pragma unroll
    for (int j = 0; j < 32; j += 8)
        t[tyi + j][txi] = src[(size_t)(by + tyi + j) * N + bx + txi];
    __syncthreads();
#pragma unroll
    for (int j = 0; j < 32; j += 8)
        dst[(size_t)(bx + tyi + j) * K + by + txi] = fsplit(t[txi][tyi + j]);
}

__global__ void convert_kernel(const float* __restrict__ in, uint32_t* __restrict__ outp, int n)
{
    for (int i = blockIdx.x * 256 + threadIdx.x; i < n; i += gridDim.x * 256)
        outp[i] = fsplit(in[i]);
}

// ================= bf16x3 mma.sync GEMM (fp32-class accuracy) ==================
#define MM_PITCH 40
#define MM_HALF  (128 * MM_PITCH)
#define MM_STAGE (2 * MM_HALF)
#define MM_SMEM  (2 * MM_STAGE * 4)

__device__ __forceinline__ void mm_load_stage(
    const uint32_t* __restrict__ A, const uint32_t* __restrict__ Bt,
    int bm, int bn, int M, int K, int k0, uint32_t* st, int tid)
{
    uint32_t a_s, b_s;
    asm("{ .reg .u64 t; cvta.to.shared.u64 t, %1; cvt.u32.u64 %0, t; }" : "=r"(a_s) : "l"(st));
    b_s = a_s + MM_HALF * 4;
#pragma unroll
    for (int j = 0; j < 4; j++) {
        int idx = tid + j * 256;
        int r = idx >> 3, c = idx & 7;
        uint32_t doff = (uint32_t)(r * MM_PITCH + c * 4) * 4;
        int grow = bm + r;
        const uint32_t* srcA = A + (size_t)(grow < M ? grow : 0) * K + k0 + c * 4;
        int szA = (grow < M) ? 16 : 0;
        asm volatile("cp.async.ca.shared.global [%0], [%1], 16, %2;"
                     :: "r"(a_s + doff), "l"(srcA), "r"(szA));
        const uint32_t* srcB = Bt + (size_t)(bn + r) * K + k0 + c * 4;
        asm volatile("cp.async.ca.shared.global [%0], [%1], 16;"
                     :: "r"(b_s + doff), "l"(srcB));
    }
    asm volatile("cp.async.commit_group;" ::: "memory");
}

#define MMA_BF16(acc, a0, a1, a2, a3, b0, b1) \
    asm volatile( \
        "mma.sync.aligned.m16n8k16.row.col.f32.bf16.bf16.f32 " \
        "{%0,%1,%2,%3}, {%4,%5,%6,%7}, {%8,%9}, {%0,%1,%2,%3};" \
        : "+f"((acc)[0]), "+f"((acc)[1]), "+f"((acc)[2]), "+f"((acc)[3]) \
        : "r"(a0), "r"(a1), "r"(a2), "r"(a3), "r"(b0), "r"(b1))

template<int EP, int OM>
__global__ __launch_bounds__(256)
void mm_gemm_kernel(const uint32_t* __restrict__ A, const uint32_t* __restrict__ Bt,
                    const float* __restrict__ bias, const float* __restrict__ res,
                    void* __restrict__ Cv, int M, int N, int K)
{
    extern __shared__ uint32_t sm[];
    const int tid = threadIdx.x;
    const int wid = tid >> 5, lane = tid & 31;
    const int wm = wid >> 2, wn = wid & 3;
    const int g = lane >> 2, t = lane & 3;
    const int bm = blockIdx.y * 128, bn = blockIdx.x * 128;

    float acc[4][4][4];
#pragma unroll
    for (int i = 0; i < 4; i++)
#pragma unroll
        for (int j = 0; j < 4; j++)
#pragma unroll
            for (int q = 0; q < 4; q++) acc[i][j][q] = 0.f;

    const int nc = K >> 5;
    mm_load_stage(A, Bt, bm, bn, M, K, 0, sm, tid);

    for (int c = 0; c < nc; c++) {
        if (c + 1 < nc)
            mm_load_stage(A, Bt, bm, bn, M, K, (c + 1) * 32, sm + ((c + 1) & 1) * MM_STAGE, tid);
        if (c + 1 < nc) asm volatile("cp.async.wait_group 1;" ::: "memory");
        else            asm volatile("cp.async.wait_group 0;" ::: "memory");
        __syncthreads();

        const uint32_t* As = sm + (c & 1) * MM_STAGE;
        const uint32_t* Bs = As + MM_HALF;
#pragma unroll
        for (int ks = 0; ks < 2; ks++) {
            uint32_t ah[4][4], al[4][4], bh[4][2], bl[4][2];
#pragma unroll
            for (int mt = 0; mt < 4; mt++) {
                const uint32_t* base = As + (wm * 64 + mt * 16 + g) * MM_PITCH + ks * 16 + 2 * t;
                ld_pair(base,                  ah[mt][0], al[mt][0]);
                ld_pair(base + 8 * MM_PITCH,   ah[mt][1], al[mt][1]);
                ld_pair(base + 8,              ah[mt][2], al[mt][2]);
                ld_pair(base + 8 * MM_PITCH + 8, ah[mt][3], al[mt][3]);
            }
#pragma unroll
            for (int nt = 0; nt < 4; nt++) {
                const uint32_t* base = Bs + (wn * 32 + nt * 8 + g) * MM_PITCH + ks * 16 + 2 * t;
                ld_pair(base,     bh[nt][0], bl[nt][0]);
                ld_pair(base + 8, bh[nt][1], bl[nt][1]);
            }
#pragma unroll
            for (int mt = 0; mt < 4; mt++)
#pragma unroll
                for (int nt = 0; nt < 4; nt++) {
                    MMA_BF16(acc[mt][nt], ah[mt][0], ah[mt][1], ah[mt][2], ah[mt][3],
                             bl[nt][0], bl[nt][1]);
                    MMA_BF16(acc[mt][nt], al[mt][0], al[mt][1], al[mt][2], al[mt][3],
                             bh[nt][0], bh[nt][1]);
                    MMA_BF16(acc[mt][nt], ah[mt][0], ah[mt][1], ah[mt][2], ah[mt][3],
                             bh[nt][0], bh[nt][1]);
                }
        }
        __syncthreads();
    }

    float* Cf = (float*)Cv;
    uint32_t* Cs = (uint32_t*)Cv;
#pragma unroll
    for (int mt = 0; mt < 4; mt++) {
#pragma unroll
        for (int half = 0; half < 2; half++) {
            int row = bm + wm * 64 + mt * 16 + g + half * 8;
            if (row >= M) continue;
#pragma unroll
            for (int nt = 0; nt < 4; nt++) {
                int col = bn + wn * 32 + nt * 8 + t * 2;
                float v0 = acc[mt][nt][half * 2 + 0] + bias[col];
                float v1 = acc[mt][nt][half * 2 + 1] + bias[col + 1];
                if (EP >= 2) {
                    v0 += res[(size_t)row * N + col];
                    v1 += res[(size_t)row * N + col + 1];
                }
                if (EP == 1) { v0 = fmaxf(v0, 0.f); v1 = fmaxf(v1, 0.f); }
                if (EP == 2) { v0 = (v0 > 0.f) ? v0 : 0.5f * v0; v1 = (v1 > 0.f) ? v1 : 0.5f * v1; }
                if (EP == 3) { v0 = (v0 > 0.f) ? v0 : expm1f(v0); v1 = (v1 > 0.f) ? v1 : expm1f(v1); }
                if (OM == 0) {
                    *(float2*)(Cf + (size_t)row * N + col) = make_float2(v0, v1);
                } else {
                    uint2 o = make_uint2(fsplit(v0), fsplit(v1));
                    *(uint2*)(Cs + (size_t)row * N + col) = o;
                }
            }
        }
    }
}

// ---------- compensated-fp32 GEMM (near-exact), q/k feeding top-k --------------
// C = relu?(A[M,K] @ B[K,N] + bias); 64x64 tile, 256 threads, 4x4 micro.
__global__ __launch_bounds__(256) void kgemm_kernel(
    const float* __restrict__ A, const float* __restrict__ B,
    const float* __restrict__ bias, float* __restrict__ C,
    int M, int N, int K, int relu)
{
    __shared__ float As[16][68];   // [k][m]
    __shared__ float Bs[16][68];   // [k][n]
    const int tid = threadIdx.x;
    const int bm = blockIdx.y * 64;
    const int bn = blockIdx.x * 64;
    const int ty = tid >> 4, tx = tid & 15;

    float s[4][4], cc[4][4];
#pragma unroll
    for (int i = 0; i < 4; i++)
#pragma unroll
        for (int j = 0; j < 4; j++) { s[i][j] = 0.f; cc[i][j] = 0.f; }

    const int ar = tid >> 2;          // 0..63
    const int ac = (tid & 3) << 2;    // 0,4,8,12
    const int br = tid >> 4;          // 0..15
    const int bc = (tid & 15) << 2;   // 0..60

    for (int k0 = 0; k0 < K; k0 += 16) {
        {
            int grow = bm + ar;
            float4 v = make_float4(0.f, 0.f, 0.f, 0.f);
            if (grow < M) v = *(const float4*)(A + (size_t)grow * K + k0 + ac);
            As[ac + 0][ar] = v.x; As[ac + 1][ar] = v.y;
            As[ac + 2][ar] = v.z; As[ac + 3][ar] = v.w;
        }
        *(float4*)&Bs[br][bc] = *(const float4*)(B + (size_t)(k0 + br) * N + bn + bc);
        __syncthreads();
#pragma unroll
        for (int kk = 0; kk < 16; kk++) {
            float4 av = *(const float4*)&As[kk][ty * 4];
            float4 bv = *(const float4*)&Bs[kk][tx * 4];
            const float* a = (const float*)&av;
            const float* b = (const float*)&bv;
#pragma unroll
            for (int i = 0; i < 4; i++)
#pragma unroll
                for (int j = 0; j < 4; j++)
                    kmac(a[i], b[j], s[i][j], cc[i][j]);
        }
        __syncthreads();
    }

#pragma unroll
    for (int i = 0; i < 4; i++) {
        int row = bm + ty * 4 + i;
        if (row < M) {
            float4 o;
            float* ov = (float*)&o;
#pragma unroll
            for (int j = 0; j < 4; j++) {
                float v = __fadd_rn(kfin(s[i][j], cc[i][j]), bias[bn + tx * 4 + j]);
                if (relu) v = fmaxf(v, 0.f);
                ov[j] = v;
            }
            *(float4*)(C + (size_t)row * N + bn + tx * 4) = o;
        }
    }
}

// ---------------- batched scores (compensated fp32, near-exact) -----------------
__global__ __launch_bounds__(256) void scores_kernel(
    const float* __restrict__ q, const float* __restrict__ k, float* __restrict__ out)
{
    int bh = blockIdx.z;
    int b = bh >> 3, h = bh & 7;
    int l0 = blockIdx.y * 32, s0 = blockIdx.x * 32;
    __shared__ float Qs[32][72];
    __shared__ float Ks[32][72];
    int tid = threadIdx.x;
    int r = tid >> 3;
    int c = (tid & 7) * 8;
    {
        int l = l0 + r;
        if (l < LL) {
            const float* src = q + ((size_t)(b * LL + l)) * DD + h * EE + c;
            *(float4*)&Qs[r][c]     = *(const float4*)src;
            *(float4*)&Qs[r][c + 4] = *(const float4*)(src + 4);
        } else {
#pragma unroll
            for (int t = 0; t < 8; t++) Qs[r][c + t] = 0.f;
        }
        int sdx = s0 + r;
        if (sdx < LL) {
            const float* src = k + ((size_t)(b * LL + sdx)) * DD + h * EE + c;
            *(float4*)&Ks[r][c]     = *(const float4*)src;
            *(float4*)&Ks[r][c + 4] = *(const float4*)(src + 4);
        } else {
#pragma unroll
            for (int t = 0; t < 8; t++) Ks[r][c + t] = 0.f;
        }
    }
    __syncthreads();
    int ty = tid >> 4, tx = tid & 15;
    float s00 = 0.f, s01 = 0.f, s10 = 0.f, s11 = 0.f;
    float c00 = 0.f, c01 = 0.f, c10 = 0.f, c11 = 0.f;
#pragma unroll 8
    for (int kk = 0; kk < EE; kk++) {
        float a0 = Qs[ty * 2 + 0][kk], a1 = Qs[ty * 2 + 1][kk];
        float b0 = Ks[tx * 2 + 0][kk], b1 = Ks[tx * 2 + 1][kk];
        kmac(a0, b0, s00, c00);
        kmac(a0, b1, s01, c01);
        kmac(a1, b0, s10, c10);
        kmac(a1, b1, s11, c11);
    }
    size_t base = (size_t)bh * LL * LL;
    int l_0 = l0 + ty * 2, s_0 = s0 + tx * 2;
    if (l_0 < LL) {
        if (s_0 < LL)     out[base + (size_t)l_0 * LL + s_0]     = kfin(s00, c00);
        if (s_0 + 1 < LL) out[base + (size_t)l_0 * LL + s_0 + 1] = kfin(s01, c01);
    }
    if (l_0 + 1 < LL) {
        if (s_0 < LL)     out[base + (size_t)(l_0 + 1) * LL + s_0]     = kfin(s10, c10);
        if (s_0 + 1 < LL) out[base + (size_t)(l_0 + 1) * LL + s_0 + 1] = kfin(s11, c11);
    }
}

// ---------------- top-k mask + softmax, in place on scores ----------------
__global__ __launch_bounds__(256) void topk_softmax_kernel(float* __restrict__ A)
{
    const int lane = threadIdx.x & 31;
    const int wslot = threadIdx.x >> 5;
    const size_t row = (size_t)blockIdx.x * 8 + wslot;
    __shared__ float sm[8][352];
    float* s = sm[wslot];
    float* rp = A + row * LL;

    float r[11];
#pragma unroll
    for (int j = 0; j < 11; j++) {
        int idx = lane + j * 32;
        float v = (idx < LL) ? rp[idx] : -INFINITY;
        r[j] = v;
        s[idx] = v;
    }
    __syncwarp();

    float kth = 0.f, mmax = 0.f;
    for (int it = 0; it < NTOPK; it++) {
        float lm = -INFINITY;
#pragma unroll
        for (int j = 0; j < 11; j++) lm = fmaxf(lm, s[lane + j * 32]);
        float gm = lm;
#pragma unroll
        for (int o = 16; o > 0; o >>= 1) gm = fmaxf(gm, __shfl_xor_sync(0xffffffffu, gm, o));
        if (it == 0) mmax = gm;
        kth = gm;
        int li = 0x7fffffff;
#pragma unroll
        for (int j = 10; j >= 0; j--) {
            int idx = lane + j * 32;
            if (s[idx] == gm) li = idx;
        }
        int gi = li;
#pragma unroll
        for (int o = 16; o > 0; o >>= 1) gi = min(gi, __shfl_xor_sync(0xffffffffu, gi, o));
        if (li == gi) s[li] = -INFINITY;
        __syncwarp();
    }

    const float scale = 0.125f;
    float e[11];
    float sum = 0.f;
#pragma unroll
    for (int j = 0; j < 11; j++) {
        int idx = lane + j * 32;
        float v = r[j];
        float t = (idx < LL && v >= kth) ? expf((v - mmax) * scale) : 0.f;
        e[j] = t;
        sum += t;
    }
#pragma unroll
    for (int o = 16; o > 0; o >>= 1) sum += __shfl_xor_sync(0xffffffffu, sum, o);
    float inv = 1.f / sum;
#pragma unroll
    for (int j = 0; j < 11; j++) {
        int idx = lane + j * 32;
        if (idx < LL) rp[idx] = e[j] * inv;
    }
}

// ---------------- A @ V -> split output -----------------------------------------
__global__ __launch_bounds__(256) void av_kernel(
    const float* __restrict__ A, const float* __restrict__ v, uint32_t* __restrict__ out)
{
    int bh = blockIdx.z;
    int b = bh >> 3, h = bh & 7;
    int l0 = blockIdx.y * 64;
    __shared__ float As2[64][17];
    __shared__ float Vs[16][65];
    int tid = threadIdx.x;
    int ty = tid >> 4, tx = tid & 15;
    float acc[4][4];
#pragma unroll
    for (int i = 0; i < 4; i++)
#pragma unroll
        for (int j = 0; j < 4; j++) acc[i][j] = 0.f;

    const int ar = tid >> 2, ac = (tid & 3) * 4;
    const int vr = tid >> 4, vc = (tid & 15) * 4;
    size_t abase = (size_t)bh * LL * LL;

    for (int s0 = 0; s0 < LL; s0 += 16) {
        int l = l0 + ar;
#pragma unroll
        for (int cc = 0; cc < 4; cc++) {
            int sidx = s0 + ac + cc;
            As2[ar][ac + cc] = (l < LL && sidx < LL) ? A[abase + (size_t)l * LL + sidx] : 0.f;
        }
        int sv = s0 + vr;
        if (sv < LL) {
            float4 t = *(const float4*)(v + ((size_t)(b * LL + sv)) * DD + h * EE + vc);
            Vs[vr][vc+0]=t.x; Vs[vr][vc+1]=t.y; Vs[vr][vc+2]=t.z; Vs[vr][vc+3]=t.w;
        } else {
#pragma unroll
            for (int t = 0; t < 4; t++) Vs[vr][vc+t] = 0.f;
        }
        __syncthreads();
#pragma unroll
        for (int kk = 0; kk < 16; kk++) {
            float a[4], bb2[4];
#pragma unroll
            for (int i = 0; i < 4; i++) a[i] = As2[ty*4+i][kk];
#pragma unroll
            for (int j = 0; j < 4; j++) bb2[j] = Vs[kk][tx*4+j];
#pragma unroll
            for (int i = 0; i < 4; i++)
#pragma unroll
                for (int j = 0; j < 4; j++) acc[i][j] = fmaf(a[i], bb2[j], acc[i][j]);
        }
        __syncthreads();
    }
#pragma unroll
    for (int i = 0; i < 4; i++) {
        int l = l0 + ty * 4 + i;
        if (l < LL) {
#pragma unroll
            for (int j = 0; j < 4; j++) {
                int e = tx * 4 + j;
                out[((size_t)(b * LL + l)) * DD + h * EE + e] = fsplit(acc[i][j]);
            }
        }
    }
}

// ---------------- pwattn1: split output -----------------------------------------
__global__ __launch_bounds__(128) void pwattn1_kernel(
    const float* __restrict__ q, const float* __restrict__ k,
    const float* __restrict__ v, uint32_t* __restrict__ out)
{
    int n = blockIdx.x;
    int l = threadIdx.x;
    __shared__ float sk[512];
    __shared__ float sv[512];
    int t4 = l * 4;
    *(float4*)&sk[t4] = *(const float4*)(k + (size_t)n * 512 + t4);
    *(float4*)&sv[t4] = *(const float4*)(v + (size_t)n * 512 + t4);
    __syncthreads();
    float qr[16];
    const float* qp = q + (size_t)n * 2048 + l * 16;
#pragma unroll
    for (int p = 0; p < 16; p++) qr[p] = qp[p];
    float sc[32];
    float m = -INFINITY;
#pragma unroll
    for (int s = 0; s < 32; s++) {
        float d = 0.f;
#pragma unroll
        for (int p = 0; p < 16; p++) d = fmaf(qr[p], sk[s * 16 + p], d);
        sc[s] = d;
        m = fmaxf(m, d);
    }
    float sum = 0.f;
    float V[16];
#pragma unroll
    for (int p = 0; p < 16; p++) V[p] = 0.f;
#pragma unroll
    for (int s = 0; s < 32; s++) {
        float w = expf((sc[s] - m) * 0.25f);
        sum += w;
#pragma unroll
        for (int p = 0; p < 16; p++) V[p] = fmaf(w, sv[s * 16 + p], V[p]);
    }
    float inv = 1.f / sum;
    uint32_t* op = out + (size_t)n * 2048 + l * 16;
#pragma unroll
    for (int p = 0; p < 16; p++) op[p] = fsplit(V[p] * inv);
}

// ---------------- pwattn2: split output -----------------------------------------
__global__ __launch_bounds__(128) void pwattn2_kernel(
    const float* __restrict__ q, const float* __restrict__ k2,
    const float* __restrict__ v2, uint32_t* __restrict__ out)
{
    int n = blockIdx.x * 4 + (threadIdx.x >> 5);
    int lane = threadIdx.x & 31;
    const float* kp = k2 + (size_t)n * 2048;
    const float* vp = v2 + (size_t)n * 2048;
    float qr[16];
    const float* qp = q + (size_t)n * 512 + lane * 16;
#pragma unroll
    for (int p = 0; p < 16; p++) qr[p] = qp[p];
    float m = -INFINITY;
    for (int s = 0; s < 128; s++) {
        float d = 0.f;
#pragma unroll
        for (int p = 0; p < 16; p++) d = fmaf(qr[p], kp[s * 16 + p], d);
        m = fmaxf(m, d);
    }
    float sum = 0.f;
    float V[16];
#pragma unroll
    for (int p = 0; p < 16; p++) V[p] = 0.f;
    for (int s = 0; s < 128; s++) {
        float d = 0.f;
#pragma unroll
        for (int p = 0; p < 16; p++) d = fmaf(qr[p], kp[s * 16 + p], d);
        float w = expf((d - m) * 0.25f);
        sum += w;
#pragma unroll
        for (int p = 0; p < 16; p++) V[p] = fmaf(w, vp[s * 16 + p], V[p]);
    }
    float inv = 1.f / sum;
    uint32_t* op = out + (size_t)n * 512 + lane * 16;
#pragma unroll
    for (int p = 0; p < 16; p++) op[p] = fsplit(V[p] * inv);
}

// ---------------- layernorm over 2048 -> split output ---------------------------
__global__ __launch_bounds__(256) void ln_kernel(
    const float* __restrict__ in, const float* __restrict__ g,
    const float* __restrict__ b, uint32_t* __restrict__ out)
{
    int n = blockIdx.x;
    int tid = threadIdx.x;
    __shared__ float red[256];
    const float* x = in + (size_t)n * 2048;
    float s = 0.f;
    for (int i = tid; i < 2048; i += 256) s += x[i];
    red[tid] = s; __syncthreads();
    for (int o = 128; o > 0; o >>= 1) { if (tid < o) red[tid] += red[tid + o]; __syncthreads(); }
    float mean = red[0] * (1.f / 2048.f);
    __syncthreads();
    float vs = 0.f;
    for (int i = tid; i < 2048; i += 256) { float d = x[i] - mean; vs += d * d; }
    red[tid] = vs; __syncthreads();
    for (int o = 128; o > 0; o >>= 1) { if (tid < o) red[tid] += red[tid + o]; __syncthreads(); }
    float var = red[0] * (1.f / 2048.f);
    float inv = rsqrtf(var + 1e-5f);
    uint32_t* op = out + (size_t)n * 2048;
    for (int i = tid; i < 2048; i += 256) op[i] = fsplit((x[i] - mean) * inv * g[i] + b[i]);
}

// ---------------- launch --------------------------------------------------------
extern "C" void kernel_launch(void* const* d_in, const int* in_sizes, int n_in,
                              void* d_out, int out_size)
{
    (void)in_sizes; (void)n_in; (void)out_size;
    const float* x     = (const float*)d_in[0];
    const float* aqw   = (const float*)d_in[1];
    const float* aqb   = (const float*)d_in[2];
    const float* akw   = (const float*)d_in[3];
    const float* akb   = (const float*)d_in[4];
    const float* avw   = (const float*)d_in[5];
    const float* avb   = (const float*)d_in[6];
    const float* aow   = (const float*)d_in[7];
    const float* aob   = (const float*)d_in[8];
    const float* encw  = (const float*)d_in[9];
    const float* encb  = (const float*)d_in[10];
    const float* f1qw  = (const float*)d_in[11];
    const float* f1qb  = (const float*)d_in[12];
    const float* f1kw  = (const float*)d_in[13];
    const float* f1kb  = (const float*)d_in[14];
    const float* f1vw  = (const float*)d_in[15];
    const float* f1vb  = (const float*)d_in[16];
    const float* f1ow  = (const float*)d_in[17];
    const float* f1ob  = (const float*)d_in[18];
    const float* f2qw  = (const float*)d_in[19];
    const float* f2qb  = (const float*)d_in[20];
    const float* f2kw  = (const float*)d_in[21];
    const float* f2kb  = (const float*)d_in[22];
    const float* f2vw  = (const float*)d_in[23];
    const float* f2vb  = (const float*)d_in[24];
    const float* f2ow  = (const float*)d_in[25];
    const float* f2ob  = (const float*)d_in[26];
    const float* lng   = (const float*)d_in[27];
    const float* lnb   = (const float*)d_in[28];

    float* out  = (float*)d_out;
    float* Aout = out + (size_t)NROWS * 512;

    float* b512; float* b2048; uint32_t* sps; uint32_t* spb; uint32_t* wt;
    cudaGetSymbolAddress((void**)&b512,  g_buf512);
    cudaGetSymbolAddress((void**)&b2048, g_buf2048);
    cudaGetSymbolAddress((void**)&sps,   g_sp_small);
    cudaGetSymbolAddress((void**)&spb,   g_sp_big);
    cudaGetSymbolAddress((void**)&wt,    g_wt);
    const size_t S = (size_t)NROWS * 512;
    const size_t T = (size_t)NROWS * 2048;
    float* qb   = b512;
    float* kb   = b512 + S;
    float* vb   = b512 + 2 * S;
    float* k1   = b512 + 3 * S;
    float* v1   = b512 + 4 * S;
    float* qu2  = b512 + 5 * S;
    float* q1   = b2048;
    float* t1   = b2048 + T;
    float* v2   = b2048 + 2 * T;
    uint32_t* x_sp   = sps;
    uint32_t* att_sp = sps + S;
    uint32_t* zb_sp  = sps + 2 * S;
    uint32_t* y2_sp  = sps + 3 * S;
    uint32_t* Vf1_sp = spb;
    uint32_t* u_sp   = spb + T;

    cudaFuncSetAttribute(mm_gemm_kernel<0,0>, cudaFuncAttributeMaxDynamicSharedMemorySize, MM_SMEM);
    cudaFuncSetAttribute(mm_gemm_kernel<1,0>, cudaFuncAttributeMaxDynamicSharedMemorySize, MM_SMEM);
    cudaFuncSetAttribute(mm_gemm_kernel<3,0>, cudaFuncAttributeMaxDynamicSharedMemorySize, MM_SMEM);
    cudaFuncSetAttribute(mm_gemm_kernel<4,0>, cudaFuncAttributeMaxDynamicSharedMemorySize, MM_SMEM);
    cudaFuncSetAttribute(mm_gemm_kernel<2,1>, cudaFuncAttributeMaxDynamicSharedMemorySize, MM_SMEM);
    cudaFuncSetAttribute(mm_gemm_kernel<0,1>, cudaFuncAttributeMaxDynamicSharedMemorySize, MM_SMEM);

    dim3 blk(256);
    dim3 tb(32, 8);
    dim3 tg512(4, (NROWS + 127) / 128);
    dim3 tg2048(16, (NROWS + 127) / 128);
    dim3 kg(8, (NROWS + 63) / 64);    // compensated fp32 gemm: 64x64 tiles, N=512

    // ---- weight transpose+split ----
    transpose_split_kernel<<<dim3(16, 16), tb>>>(avw,  wt + OFF_AV,  512,  512);
    transpose_split_kernel<<<dim3(16, 16), tb>>>(aow,  wt + OFF_AO,  512,  512);
    transpose_split_kernel<<<dim3(16, 16), tb>>>(encw, wt + OFF_ENC, 512,  512);
    transpose_split_kernel<<<dim3(64, 16), tb>>>(f1qw, wt + OFF_F1Q, 512,  2048);
    transpose_split_kernel<<<dim3(16, 16), tb>>>(f1kw, wt + OFF_F1K, 512,  512);
    transpose_split_kernel<<<dim3(16, 16), tb>>>(f1vw, wt + OFF_F1V, 512,  512);
    transpose_split_kernel<<<dim3(64, 64), tb>>>(f1ow, wt + OFF_F1O, 2048, 2048);
    transpose_split_kernel<<<dim3(16, 64), tb>>>(f2qw, wt + OFF_F2Q, 2048, 512);
    transpose_split_kernel<<<dim3(64, 64), tb>>>(f2kw, wt + OFF_F2K, 2048, 2048);
    transpose_split_kernel<<<dim3(64, 64), tb>>>(f2vw, wt + OFF_F2V, 2048, 2048);
    transpose_split_kernel<<<dim3(16, 16), tb>>>(f2ow, wt + OFF_F2O, 512,  512);
    convert_kernel<<<4096, 256>>>(x, x_sp, (int)S);

    // ---- graph attention (q,k,scores near-exact compensated fp32) ----
    kgemm_kernel<<<kg, blk>>>(x, aqw, aqb, qb, NROWS, 512, 512, 1);
    kgemm_kernel<<<kg, blk>>>(x, akw, akb, kb, NROWS, 512, 512, 0);
    mm_gemm_kernel<1,0><<<tg512, blk, MM_SMEM>>>(x_sp, wt + OFF_AV, avb, nullptr, vb, NROWS, 512, 512);
    scores_kernel<<<dim3(11, 11, 512), blk>>>(qb, kb, Aout);
    topk_softmax_kernel<<<20544, blk>>>(Aout);
    av_kernel<<<dim3(1, 6, 512), blk>>>(Aout, vb, att_sp);
    mm_gemm_kernel<2,1><<<tg512, blk, MM_SMEM>>>(att_sp, wt + OFF_AO, aob, x, zb_sp, NROWS, 512, 512);
    mm_gemm_kernel<0,1><<<tg512, blk, MM_SMEM>>>(zb_sp, wt + OFF_ENC, encb, nullptr, y2_sp, NROWS, 512, 512);

    // ---- ff1 pwattn ----
    mm_gemm_kernel<1,0><<<tg2048, blk, MM_SMEM>>>(y2_sp, wt + OFF_F1Q, f1qb, nullptr, q1, NROWS, 2048, 512);
    mm_gemm_kernel<0,0><<<tg512, blk, MM_SMEM>>>(y2_sp, wt + OFF_F1K, f1kb, nullptr, k1, NROWS, 512, 512);
    mm_gemm_kernel<1,0><<<tg512, blk, MM_SMEM>>>(y2_sp, wt + OFF_F1V, f1vb, nullptr, v1, NROWS, 512, 512);
    pwattn1_kernel<<<NROWS, 128>>>(q1, k1, v1, Vf1_sp);
    mm_gemm_kernel<3,0><<<tg2048, blk, MM_SMEM>>>(Vf1_sp, wt + OFF_F1O, f1ob, q1, t1, NROWS, 2048, 2048);
    ln_kernel<<<NROWS, blk>>>(t1, lng, lnb, u_sp);

    // ---- ff2 pwattn ----
    mm_gemm_kernel<1,0><<<tg512, blk, MM_SMEM>>>(u_sp, wt + OFF_F2Q, f2qb, nullptr, qu2, NROWS, 512, 2048);
    mm_gemm_kernel<0,0><<<tg2048, blk, MM_SMEM>>>(u_sp, wt + OFF_F2K, f2kb, nullptr, q1, NROWS, 2048, 2048);
    mm_gemm_kernel<1,0><<<tg2048, blk, MM_SMEM>>>(u_sp, wt + OFF_F2V, f2vb, nullptr, v2, NROWS, 2048, 2048);
    pwattn2_kernel<<<NROWS / 4, 128>>>(qu2, q1, v2, x_sp);
    mm_gemm_kernel<4,0><<<tg512, blk, MM_SMEM>>>(x_sp, wt + OFF_F2O, f2ob, qu2, out, NROWS, 512, 512);
}

// round 9
// speedup vs baseline: 4.5230x; 1.1788x over previous
#include <cuda_runtime.h>
#include <cuda_bf16.h>
#include <math.h>
#include <stdint.h>

#define NROWS 20544     // B*L = 64*321
#define LL 321
#define DD 512
#define HH 8
#define EE 64
#define NTOPK 10

// ---------------- scratch (allocation-free: __device__ globals) ----------------
__device__ float    g_buf512[6ULL * NROWS * 512];    // f32: qb,kb,vb,k1,v1,qu2
__device__ float    g_buf2048[4ULL * NROWS * 2048];  // f32: q1/k2, t1, v2, spare
__device__ uint32_t g_sp_small[4ULL * NROWS * 512];  // split: x/att2, att, zb, y2
__device__ uint32_t g_sp_big[2ULL * NROWS * 2048];   // split: Vf1, u
__device__ uint32_t g_wt[16252928];                  // split transposed weights [N,K]

#define OFF_AV   0u
#define OFF_AO   262144u
#define OFF_ENC  524288u
#define OFF_F1Q  786432u
#define OFF_F1K  1835008u
#define OFF_F1V  2097152u
#define OFF_F1O  2359296u
#define OFF_F2Q  6553600u
#define OFF_F2K  7602176u
#define OFF_F2V  11796480u
#define OFF_F2O  15990784u

// ---------------- bf16 split helpers -------------------------------------------
__device__ __forceinline__ uint32_t fsplit(float x) {
    __nv_bfloat16 h = __float2bfloat16(x);
    float hf = __bfloat162float(h);
    __nv_bfloat16 l = __float2bfloat16(x - hf);
    return (uint32_t)__bfloat16_as_ushort(h) | ((uint32_t)__bfloat16_as_ushort(l) << 16);
}
__device__ __forceinline__ void ld_pair(const uint32_t* s, uint32_t& hi, uint32_t& lo) {
    uint2 p = *(const uint2*)s;
    hi = __byte_perm(p.x, p.y, 0x5410);
    lo = __byte_perm(p.x, p.y, 0x7632);
}

// ------------- blocked compensation: Kahan-merge a block partial ---------------
__device__ __forceinline__ void kadd(float p, float& s, float& c) {
    float y = __fsub_rn(p, c);
    float t = __fadd_rn(s, y);
    c = __fsub_rn(__fsub_rn(t, s), y);
    s = t;
}
__device__ __forceinline__ float kfin(float s, float c) { return __fsub_rn(s, c); }

// ============================ weight transpose + split =========================
__global__ void transpose_split_kernel(const float* __restrict__ src, uint32_t* __restrict__ dst,
                                       int K, int N)
{
    __shared__ float t[32][33];
    int bx = blockIdx.x * 32, by = blockIdx.y * 32;
    int txi = threadIdx.x, tyi = threadIdx.y;
#pragma unroll
    for (int j = 0; j < 32; j += 8)
        t[tyi + j][txi] = src[(size_t)(by + tyi + j) * N + bx + txi];
    __syncthreads();
#pragma unroll
    for (int j = 0; j < 32; j += 8)
        dst[(size_t)(bx + tyi + j) * K + by + txi] = fsplit(t[txi][tyi + j]);
}

__global__ void convert_kernel(const float* __restrict__ in, uint32_t* __restrict__ outp, int n)
{
    for (int i = blockIdx.x * 256 + threadIdx.x; i < n; i += gridDim.x * 256)
        outp[i] = fsplit(in[i]);
}

// ================= bf16x3 mma.sync GEMM (fp32-class accuracy) ==================
#define MM_PITCH 40
#define MM_HALF  (128 * MM_PITCH)
#define MM_STAGE (2 * MM_HALF)
#define MM_SMEM  (2 * MM_STAGE * 4)

__device__ __forceinline__ void mm_load_stage(
    const uint32_t* __restrict__ A, const uint32_t* __restrict__ Bt,
    int bm, int bn, int M, int K, int k0, uint32_t* st, int tid)
{
    uint32_t a_s, b_s;
    asm("{ .reg .u64 t; cvta.to.shared.u64 t, %1; cvt.u32.u64 %0, t; }" : "=r"(a_s) : "l"(st));
    b_s = a_s + MM_HALF * 4;
#pragma unroll
    for (int j = 0; j < 4; j++) {
        int idx = tid + j * 256;
        int r = idx >> 3, c = idx & 7;
        uint32_t doff = (uint32_t)(r * MM_PITCH + c * 4) * 4;
        int grow = bm + r;
        const uint32_t* srcA = A + (size_t)(grow < M ? grow : 0) * K + k0 + c * 4;
        int szA = (grow < M) ? 16 : 0;
        asm volatile("cp.async.ca.shared.global [%0], [%1], 16, %2;"
                     :: "r"(a_s + doff), "l"(srcA), "r"(szA));
        const uint32_t* srcB = Bt + (size_t)(bn + r) * K + k0 + c * 4;
        asm volatile("cp.async.ca.shared.global [%0], [%1], 16;"
                     :: "r"(b_s + doff), "l"(srcB));
    }
    asm volatile("cp.async.commit_group;" ::: "memory");
}

#define MMA_BF16(acc, a0, a1, a2, a3, b0, b1) \
    asm volatile( \
        "mma.sync.aligned.m16n8k16.row.col.f32.bf16.bf16.f32 " \
        "{%0,%1,%2,%3}, {%4,%5,%6,%7}, {%8,%9}, {%0,%1,%2,%3};" \
        : "+f"((acc)[0]), "+f"((acc)[1]), "+f"((acc)[2]), "+f"((acc)[3]) \
        : "r"(a0), "r"(a1), "r"(a2), "r"(a3), "r"(b0), "r"(b1))

template<int EP, int OM>
__global__ __launch_bounds__(256)
void mm_gemm_kernel(const uint32_t* __restrict__ A, const uint32_t* __restrict__ Bt,
                    const float* __restrict__ bias, const float* __restrict__ res,
                    void* __restrict__ Cv, int M, int N, int K)
{
    extern __shared__ uint32_t sm[];
    const int tid = threadIdx.x;
    const int wid = tid >> 5, lane = tid & 31;
    const int wm = wid >> 2, wn = wid & 3;
    const int g = lane >> 2, t = lane & 3;
    const int bm = blockIdx.y * 128, bn = blockIdx.x * 128;

    float acc[4][4][4];
#pragma unroll
    for (int i = 0; i < 4; i++)
#pragma unroll
        for (int j = 0; j < 4; j++)
#pragma unroll
            for (int q = 0; q < 4; q++) acc[i][j][q] = 0.f;

    const int nc = K >> 5;
    mm_load_stage(A, Bt, bm, bn, M, K, 0, sm, tid);

    for (int c = 0; c < nc; c++) {
        if (c + 1 < nc)
            mm_load_stage(A, Bt, bm, bn, M, K, (c + 1) * 32, sm + ((c + 1) & 1) * MM_STAGE, tid);
        if (c + 1 < nc) asm volatile("cp.async.wait_group 1;" ::: "memory");
        else            asm volatile("cp.async.wait_group 0;" ::: "memory");
        __syncthreads();

        const uint32_t* As = sm + (c & 1) * MM_STAGE;
        const uint32_t* Bs = As + MM_HALF;
#pragma unroll
        for (int ks = 0; ks < 2; ks++) {
            uint32_t ah[4][4], al[4][4], bh[4][2], bl[4][2];
#pragma unroll
            for (int mt = 0; mt < 4; mt++) {
                const uint32_t* base = As + (wm * 64 + mt * 16 + g) * MM_PITCH + ks * 16 + 2 * t;
                ld_pair(base,                  ah[mt][0], al[mt][0]);
                ld_pair(base + 8 * MM_PITCH,   ah[mt][1], al[mt][1]);
                ld_pair(base + 8,              ah[mt][2], al[mt][2]);
                ld_pair(base + 8 * MM_PITCH + 8, ah[mt][3], al[mt][3]);
            }
#pragma unroll
            for (int nt = 0; nt < 4; nt++) {
                const uint32_t* base = Bs + (wn * 32 + nt * 8 + g) * MM_PITCH + ks * 16 + 2 * t;
                ld_pair(base,     bh[nt][0], bl[nt][0]);
                ld_pair(base + 8, bh[nt][1], bl[nt][1]);
            }
#pragma unroll
            for (int mt = 0; mt < 4; mt++)
#pragma unroll
                for (int nt = 0; nt < 4; nt++) {
                    MMA_BF16(acc[mt][nt], ah[mt][0], ah[mt][1], ah[mt][2], ah[mt][3],
                             bl[nt][0], bl[nt][1]);
                    MMA_BF16(acc[mt][nt], al[mt][0], al[mt][1], al[mt][2], al[mt][3],
                             bh[nt][0], bh[nt][1]);
                    MMA_BF16(acc[mt][nt], ah[mt][0], ah[mt][1], ah[mt][2], ah[mt][3],
                             bh[nt][0], bh[nt][1]);
                }
        }
        __syncthreads();
    }

    float* Cf = (float*)Cv;
    uint32_t* Cs = (uint32_t*)Cv;
#pragma unroll
    for (int mt = 0; mt < 4; mt++) {
#pragma unroll
        for (int half = 0; half < 2; half++) {
            int row = bm + wm * 64 + mt * 16 + g + half * 8;
            if (row >= M) continue;
#pragma unroll
            for (int nt = 0; nt < 4; nt++) {
                int col = bn + wn * 32 + nt * 8 + t * 2;
                float v0 = acc[mt][nt][half * 2 + 0] + bias[col];
                float v1 = acc[mt][nt][half * 2 + 1] + bias[col + 1];
                if (EP >= 2) {
                    v0 += res[(size_t)row * N + col];
                    v1 += res[(size_t)row * N + col + 1];
                }
                if (EP == 1) { v0 = fmaxf(v0, 0.f); v1 = fmaxf(v1, 0.f); }
                if (EP == 2) { v0 = (v0 > 0.f) ? v0 : 0.5f * v0; v1 = (v1 > 0.f) ? v1 : 0.5f * v1; }
                if (EP == 3) { v0 = (v0 > 0.f) ? v0 : expm1f(v0); v1 = (v1 > 0.f) ? v1 : expm1f(v1); }
                if (OM == 0) {
                    *(float2*)(Cf + (size_t)row * N + col) = make_float2(v0, v1);
                } else {
                    uint2 o = make_uint2(fsplit(v0), fsplit(v1));
                    *(uint2*)(Cs + (size_t)row * N + col) = o;
                }
            }
        }
    }
}

// ---------- blocked-compensated fp32 GEMM (near-exact), q/k feeding top-k ------
// Plain FMA inside 8-length blocks, Kahan-merge per block: ~1.5 ops/MAC,
// residual sigma ~1.5e-7 relative (<< reference's own fp32 noise).
__global__ __launch_bounds__(256) void kgemm_kernel(
    const float* __restrict__ A, const float* __restrict__ B,
    const float* __restrict__ bias, float* __restrict__ C,
    int M, int N, int K, int relu)
{
    __shared__ float As[16][68];   // [k][m]
    __shared__ float Bs[16][68];   // [k][n]
    const int tid = threadIdx.x;
    const int bm = blockIdx.y * 64;
    const int bn = blockIdx.x * 64;
    const int ty = tid >> 4, tx = tid & 15;

    float s[4][4], cc[4][4];
#pragma unroll
    for (int i = 0; i < 4; i++)
#pragma unroll
        for (int j = 0; j < 4; j++) { s[i][j] = 0.f; cc[i][j] = 0.f; }

    const int ar = tid >> 2;          // 0..63
    const int ac = (tid & 3) << 2;    // 0,4,8,12
    const int br = tid >> 4;          // 0..15
    const int bc = (tid & 15) << 2;   // 0..60

    for (int k0 = 0; k0 < K; k0 += 16) {
        {
            int grow = bm + ar;
            float4 v = make_float4(0.f, 0.f, 0.f, 0.f);
            if (grow < M) v = *(const float4*)(A + (size_t)grow * K + k0 + ac);
            As[ac + 0][ar] = v.x; As[ac + 1][ar] = v.y;
            As[ac + 2][ar] = v.z; As[ac + 3][ar] = v.w;
        }
        *(float4*)&Bs[br][bc] = *(const float4*)(B + (size_t)(k0 + br) * N + bn + bc);
        __syncthreads();
#pragma unroll
        for (int blkk = 0; blkk < 2; blkk++) {
            float p[4][4];
#pragma unroll
            for (int i = 0; i < 4; i++)
#pragma unroll
                for (int j = 0; j < 4; j++) p[i][j] = 0.f;
#pragma unroll
            for (int kk = blkk * 8; kk < blkk * 8 + 8; kk++) {
                float4 av = *(const float4*)&As[kk][ty * 4];
                float4 bv = *(const float4*)&Bs[kk][tx * 4];
                const float* a = (const float*)&av;
                const float* b = (const float*)&bv;
#pragma unroll
                for (int i = 0; i < 4; i++)
#pragma unroll
                    for (int j = 0; j < 4; j++)
                        p[i][j] = __fmaf_rn(a[i], b[j], p[i][j]);
            }
#pragma unroll
            for (int i = 0; i < 4; i++)
#pragma unroll
                for (int j = 0; j < 4; j++)
                    kadd(p[i][j], s[i][j], cc[i][j]);
        }
        __syncthreads();
    }

#pragma unroll
    for (int i = 0; i < 4; i++) {
        int row = bm + ty * 4 + i;
        if (row < M) {
            float4 o;
            float* ov = (float*)&o;
#pragma unroll
            for (int j = 0; j < 4; j++) {
                float v = __fadd_rn(kfin(s[i][j], cc[i][j]), bias[bn + tx * 4 + j]);
                if (relu) v = fmaxf(v, 0.f);
                ov[j] = v;
            }
            *(float4*)(C + (size_t)row * N + bn + tx * 4) = o;
        }
    }
}

// ---------------- batched scores (blocked-compensated fp32) ---------------------
__global__ __launch_bounds__(256) void scores_kernel(
    const float* __restrict__ q, const float* __restrict__ k, float* __restrict__ out)
{
    int bh = blockIdx.z;
    int b = bh >> 3, h = bh & 7;
    int l0 = blockIdx.y * 32, s0 = blockIdx.x * 32;
    __shared__ float Qs[32][72];
    __shared__ float Ks[32][72];
    int tid = threadIdx.x;
    int r = tid >> 3;
    int c = (tid & 7) * 8;
    {
        int l = l0 + r;
        if (l < LL) {
            const float* src = q + ((size_t)(b * LL + l)) * DD + h * EE + c;
            *(float4*)&Qs[r][c]     = *(const float4*)src;
            *(float4*)&Qs[r][c + 4] = *(const float4*)(src + 4);
        } else {
#pragma unroll
            for (int t = 0; t < 8; t++) Qs[r][c + t] = 0.f;
        }
        int sdx = s0 + r;
        if (sdx < LL) {
            const float* src = k + ((size_t)(b * LL + sdx)) * DD + h * EE + c;
            *(float4*)&Ks[r][c]     = *(const float4*)src;
            *(float4*)&Ks[r][c + 4] = *(const float4*)(src + 4);
        } else {
#pragma unroll
            for (int t = 0; t < 8; t++) Ks[r][c + t] = 0.f;
        }
    }
    __syncthreads();
    int ty = tid >> 4, tx = tid & 15;
    float s00 = 0.f, s01 = 0.f, s10 = 0.f, s11 = 0.f;
    float c00 = 0.f, c01 = 0.f, c10 = 0.f, c11 = 0.f;
#pragma unroll
    for (int blkk = 0; blkk < 8; blkk++) {
        float p00 = 0.f, p01 = 0.f, p10 = 0.f, p11 = 0.f;
#pragma unroll
        for (int kk = blkk * 8; kk < blkk * 8 + 8; kk++) {
            float a0 = Qs[ty * 2 + 0][kk], a1 = Qs[ty * 2 + 1][kk];
            float b0 = Ks[tx * 2 + 0][kk], b1 = Ks[tx * 2 + 1][kk];
            p00 = __fmaf_rn(a0, b0, p00);
            p01 = __fmaf_rn(a0, b1, p01);
            p10 = __fmaf_rn(a1, b0, p10);
            p11 = __fmaf_rn(a1, b1, p11);
        }
        kadd(p00, s00, c00);
        kadd(p01, s01, c01);
        kadd(p10, s10, c10);
        kadd(p11, s11, c11);
    }
    size_t base = (size_t)bh * LL * LL;
    int l_0 = l0 + ty * 2, s_0 = s0 + tx * 2;
    if (l_0 < LL) {
        if (s_0 < LL)     out[base + (size_t)l_0 * LL + s_0]     = kfin(s00, c00);
        if (s_0 + 1 < LL) out[base + (size_t)l_0 * LL + s_0 + 1] = kfin(s01, c01);
    }
    if (l_0 + 1 < LL) {
        if (s_0 < LL)     out[base + (size_t)(l_0 + 1) * LL + s_0]     = kfin(s10, c10);
        if (s_0 + 1 < LL) out[base + (size_t)(l_0 + 1) * LL + s_0 + 1] = kfin(s11, c11);
    }
}

// ---------------- top-k mask + softmax, in place on scores ----------------
__global__ __launch_bounds__(256) void topk_softmax_kernel(float* __restrict__ A)
{
    const int lane = threadIdx.x & 31;
    const int wslot = threadIdx.x >> 5;
    const size_t row = (size_t)blockIdx.x * 8 + wslot;
    __shared__ float sm[8][352];
    float* s = sm[wslot];
    float* rp = A + row * LL;

    float r[11];
#pragma unroll
    for (int j = 0; j < 11; j++) {
        int idx = lane + j * 32;
        float v = (idx < LL) ? rp[idx] : -INFINITY;
        r[j] = v;
        s[idx] = v;
    }
    __syncwarp();

    float kth = 0.f, mmax = 0.f;
    for (int it = 0; it < NTOPK; it++) {
        float lm = -INFINITY;
#pragma unroll
        for (int j = 0; j < 11; j++) lm = fmaxf(lm, s[lane + j * 32]);
        float gm = lm;
#pragma unroll
        for (int o = 16; o > 0; o >>= 1) gm = fmaxf(gm, __shfl_xor_sync(0xffffffffu, gm, o));
        if (it == 0) mmax = gm;
        kth = gm;
        int li = 0x7fffffff;
#pragma unroll
        for (int j = 10; j >= 0; j--) {
            int idx = lane + j * 32;
            if (s[idx] == gm) li = idx;
        }
        int gi = li;
#pragma unroll
        for (int o = 16; o > 0; o >>= 1) gi = min(gi, __shfl_xor_sync(0xffffffffu, gi, o));
        if (li == gi) s[li] = -INFINITY;
        __syncwarp();
    }

    const float scale = 0.125f;
    float e[11];
    float sum = 0.f;
#pragma unroll
    for (int j = 0; j < 11; j++) {
        int idx = lane + j * 32;
        float v = r[j];
        float t = (idx < LL && v >= kth) ? expf((v - mmax) * scale) : 0.f;
        e[j] = t;
        sum += t;
    }
#pragma unroll
    for (int o = 16; o > 0; o >>= 1) sum += __shfl_xor_sync(0xffffffffu, sum, o);
    float inv = 1.f / sum;
#pragma unroll
    for (int j = 0; j < 11; j++) {
        int idx = lane + j * 32;
        if (idx < LL) rp[idx] = e[j] * inv;
    }
}

// ---------------- A @ V -> split output -----------------------------------------
__global__ __launch_bounds__(256) void av_kernel(
    const float* __restrict__ A, const float* __restrict__ v, uint32_t* __restrict__ out)
{
    int bh = blockIdx.z;
    int b = bh >> 3, h = bh & 7;
    int l0 = blockIdx.y * 64;
    __shared__ float As2[64][17];
    __shared__ float Vs[16][65];
    int tid = threadIdx.x;
    int ty = tid >> 4, tx = tid & 15;
    float acc[4][4];
#pragma unroll
    for (int i = 0; i < 4; i++)
#pragma unroll
        for (int j = 0; j < 4; j++) acc[i][j] = 0.f;

    const int ar = tid >> 2, ac = (tid & 3) * 4;
    const int vr = tid >> 4, vc = (tid & 15) * 4;
    size_t abase = (size_t)bh * LL * LL;

    for (int s0 = 0; s0 < LL; s0 += 16) {
        int l = l0 + ar;
#pragma unroll
        for (int cc = 0; cc < 4; cc++) {
            int sidx = s0 + ac + cc;
            As2[ar][ac + cc] = (l < LL && sidx < LL) ? A[abase + (size_t)l * LL + sidx] : 0.f;
        }
        int sv = s0 + vr;
        if (sv < LL) {
            float4 t = *(const float4*)(v + ((size_t)(b * LL + sv)) * DD + h * EE + vc);
            Vs[vr][vc+0]=t.x; Vs[vr][vc+1]=t.y; Vs[vr][vc+2]=t.z; Vs[vr][vc+3]=t.w;
        } else {
#pragma unroll
            for (int t = 0; t < 4; t++) Vs[vr][vc+t] = 0.f;
        }
        __syncthreads();
#pragma unroll
        for (int kk = 0; kk < 16; kk++) {
            float a[4], bb2[4];
#pragma unroll
            for (int i = 0; i < 4; i++) a[i] = As2[ty*4+i][kk];
#pragma unroll
            for (int j = 0; j < 4; j++) bb2[j] = Vs[kk][tx*4+j];
#pragma unroll
            for (int i = 0; i < 4; i++)
#pragma unroll
                for (int j = 0; j < 4; j++) acc[i][j] = fmaf(a[i], bb2[j], acc[i][j]);
        }
        __syncthreads();
    }
#pragma unroll
    for (int i = 0; i < 4; i++) {
        int l = l0 + ty * 4 + i;
        if (l < LL) {
#pragma unroll
            for (int j = 0; j < 4; j++) {
                int e = tx * 4 + j;
                out[((size_t)(b * LL + l)) * DD + h * EE + e] = fsplit(acc[i][j]);
            }
        }
    }
}

// ---------------- pwattn1: split output -----------------------------------------
__global__ __launch_bounds__(128) void pwattn1_kernel(
    const float* __restrict__ q, const float* __restrict__ k,
    const float* __restrict__ v, uint32_t* __restrict__ out)
{
    int n = blockIdx.x;
    int l = threadIdx.x;
    __shared__ float sk[512];
    __shared__ float sv[512];
    int t4 = l * 4;
    *(float4*)&sk[t4] = *(const float4*)(k + (size_t)n * 512 + t4);
    *(float4*)&sv[t4] = *(const float4*)(v + (size_t)n * 512 + t4);
    __syncthreads();
    float qr[16];
    const float* qp = q + (size_t)n * 2048 + l * 16;
#pragma unroll
    for (int p = 0; p < 16; p++) qr[p] = qp[p];
    float sc[32];
    float m = -INFINITY;
#pragma unroll
    for (int s = 0; s < 32; s++) {
        float d = 0.f;
#pragma unroll
        for (int p = 0; p < 16; p++) d = fmaf(qr[p], sk[s * 16 + p], d);
        sc[s] = d;
        m = fmaxf(m, d);
    }
    float sum = 0.f;
    float V[16];
#pragma unroll
    for (int p = 0; p < 16; p++) V[p] = 0.f;
#pragma unroll
    for (int s = 0; s < 32; s++) {
        float w = expf((sc[s] - m) * 0.25f);
        sum += w;
#pragma unroll
        for (int p = 0; p < 16; p++) V[p] = fmaf(w, sv[s * 16 + p], V[p]);
    }
    float inv = 1.f / sum;
    uint32_t* op = out + (size_t)n * 2048 + l * 16;
#pragma unroll
    for (int p = 0; p < 16; p++) op[p] = fsplit(V[p] * inv);
}

// ---------------- pwattn2: split output -----------------------------------------
__global__ __launch_bounds__(128) void pwattn2_kernel(
    const float* __restrict__ q, const float* __restrict__ k2,
    const float* __restrict__ v2, uint32_t* __restrict__ out)
{
    int n = blockIdx.x * 4 + (threadIdx.x >> 5);
    int lane = threadIdx.x & 31;
    const float* kp = k2 + (size_t)n * 2048;
    const float* vp = v2 + (size_t)n * 2048;
    float qr[16];
    const float* qp = q + (size_t)n * 512 + lane * 16;
#pragma unroll
    for (int p = 0; p < 16; p++) qr[p] = qp[p];
    float m = -INFINITY;
    for (int s = 0; s < 128; s++) {
        float d = 0.f;
#pragma unroll
        for (int p = 0; p < 16; p++) d = fmaf(qr[p], kp[s * 16 + p], d);
        m = fmaxf(m, d);
    }
    float sum = 0.f;
    float V[16];
#pragma unroll
    for (int p = 0; p < 16; p++) V[p] = 0.f;
    for (int s = 0; s < 128; s++) {
        float d = 0.f;
#pragma unroll
        for (int p = 0; p < 16; p++) d = fmaf(qr[p], kp[s * 16 + p], d);
        float w = expf((d - m) * 0.25f);
        sum += w;
#pragma unroll
        for (int p = 0; p < 16; p++) V[p] = fmaf(w, vp[s * 16 + p], V[p]);
    }
    float inv = 1.f / sum;
    uint32_t* op = out + (size_t)n * 512 + lane * 16;
#pragma unroll
    for (int p = 0; p < 16; p++) op[p] = fsplit(V[p] * inv);
}

// ---------------- layernorm over 2048 -> split output ---------------------------
__global__ __launch_bounds__(256) void ln_kernel(
    const float* __restrict__ in, const float* __restrict__ g,
    const float* __restrict__ b, uint32_t* __restrict__ out)
{
    int n = blockIdx.x;
    int tid = threadIdx.x;
    __shared__ float red[256];
    const float* x = in + (size_t)n * 2048;
    float s = 0.f;
    for (int i = tid; i < 2048; i += 256) s += x[i];
    red[tid] = s; __syncthreads();
    for (int o = 128; o > 0; o >>= 1) { if (tid < o) red[tid] += red[tid + o]; __syncthreads(); }
    float mean = red[0] * (1.f / 2048.f);
    __syncthreads();
    float vs = 0.f;
    for (int i = tid; i < 2048; i += 256) { float d = x[i] - mean; vs += d * d; }
    red[tid] = vs; __syncthreads();
    for (int o = 128; o > 0; o >>= 1) { if (tid < o) red[tid] += red[tid + o]; __syncthreads(); }
    float var = red[0] * (1.f / 2048.f);
    float inv = rsqrtf(var + 1e-5f);
    uint32_t* op = out + (size_t)n * 2048;
    for (int i = tid; i < 2048; i += 256) op[i] = fsplit((x[i] - mean) * inv * g[i] + b[i]);
}

// ---------------- launch --------------------------------------------------------
extern "C" void kernel_launch(void* const* d_in, const int* in_sizes, int n_in,
                              void* d_out, int out_size)
{
    (void)in_sizes; (void)n_in; (void)out_size;
    const float* x     = (const float*)d_in[0];
    const float* aqw   = (const float*)d_in[1];
    const float* aqb   = (const float*)d_in[2];
    const float* akw   = (const float*)d_in[3];
    const float* akb   = (const float*)d_in[4];
    const float* avw   = (const float*)d_in[5];
    const float* avb   = (const float*)d_in[6];
    const float* aow   = (const float*)d_in[7];
    const float* aob   = (const float*)d_in[8];
    const float* encw  = (const float*)d_in[9];
    const float* encb  = (const float*)d_in[10];
    const float* f1qw  = (const float*)d_in[11];
    const float* f1qb  = (const float*)d_in[12];
    const float* f1kw  = (const float*)d_in[13];
    const float* f1kb  = (const float*)d_in[14];
    const float* f1vw  = (const float*)d_in[15];
    const float* f1vb  = (const float*)d_in[16];
    const float* f1ow  = (const float*)d_in[17];
    const float* f1ob  = (const float*)d_in[18];
    const float* f2qw  = (const float*)d_in[19];
    const float* f2qb  = (const float*)d_in[20];
    const float* f2kw  = (const float*)d_in[21];
    const float* f2kb  = (const float*)d_in[22];
    const float* f2vw  = (const float*)d_in[23];
    const float* f2vb  = (const float*)d_in[24];
    const float* f2ow  = (const float*)d_in[25];
    const float* f2ob  = (const float*)d_in[26];
    const float* lng   = (const float*)d_in[27];
    const float* lnb   = (const float*)d_in[28];

    float* out  = (float*)d_out;
    float* Aout = out + (size_t)NROWS * 512;

    float* b512; float* b2048; uint32_t* sps; uint32_t* spb; uint32_t* wt;
    cudaGetSymbolAddress((void**)&b512,  g_buf512);
    cudaGetSymbolAddress((void**)&b2048, g_buf2048);
    cudaGetSymbolAddress((void**)&sps,   g_sp_small);
    cudaGetSymbolAddress((void**)&spb,   g_sp_big);
    cudaGetSymbolAddress((void**)&wt,    g_wt);
    const size_t S = (size_t)NROWS * 512;
    const size_t T = (size_t)NROWS * 2048;
    float* qb   = b512;
    float* kb   = b512 + S;
    float* vb   = b512 + 2 * S;
    float* k1   = b512 + 3 * S;
    float* v1   = b512 + 4 * S;
    float* qu2  = b512 + 5 * S;
    float* q1   = b2048;
    float* t1   = b2048 + T;
    float* v2   = b2048 + 2 * T;
    uint32_t* x_sp   = sps;
    uint32_t* att_sp = sps + S;
    uint32_t* zb_sp  = sps + 2 * S;
    uint32_t* y2_sp  = sps + 3 * S;
    uint32_t* Vf1_sp = spb;
    uint32_t* u_sp   = spb + T;

    cudaFuncSetAttribute(mm_gemm_kernel<0,0>, cudaFuncAttributeMaxDynamicSharedMemorySize, MM_SMEM);
    cudaFuncSetAttribute(mm_gemm_kernel<1,0>, cudaFuncAttributeMaxDynamicSharedMemorySize, MM_SMEM);
    cudaFuncSetAttribute(mm_gemm_kernel<3,0>, cudaFuncAttributeMaxDynamicSharedMemorySize, MM_SMEM);
    cudaFuncSetAttribute(mm_gemm_kernel<4,0>, cudaFuncAttributeMaxDynamicSharedMemorySize, MM_SMEM);
    cudaFuncSetAttribute(mm_gemm_kernel<2,1>, cudaFuncAttributeMaxDynamicSharedMemorySize, MM_SMEM);
    cudaFuncSetAttribute(mm_gemm_kernel<0,1>, cudaFuncAttributeMaxDynamicSharedMemorySize, MM_SMEM);

    dim3 blk(256);
    dim3 tb(32, 8);
    dim3 tg512(4, (NROWS + 127) / 128);
    dim3 tg2048(16, (NROWS + 127) / 128);
    dim3 kg(8, (NROWS + 63) / 64);

    // ---- weight transpose+split ----
    transpose_split_kernel<<<dim3(16, 16), tb>>>(avw,  wt + OFF_AV,  512,  512);
    transpose_split_kernel<<<dim3(16, 16), tb>>>(aow,  wt + OFF_AO,  512,  512);
    transpose_split_kernel<<<dim3(16, 16), tb>>>(encw, wt + OFF_ENC, 512,  512);
    transpose_split_kernel<<<dim3(64, 16), tb>>>(f1qw, wt + OFF_F1Q, 512,  2048);
    transpose_split_kernel<<<dim3(16, 16), tb>>>(f1kw, wt + OFF_F1K, 512,  512);
    transpose_split_kernel<<<dim3(16, 16), tb>>>(f1vw, wt + OFF_F1V, 512,  512);
    transpose_split_kernel<<<dim3(64, 64), tb>>>(f1ow, wt + OFF_F1O, 2048, 2048);
    transpose_split_kernel<<<dim3(16, 64), tb>>>(f2qw, wt + OFF_F2Q, 2048, 512);
    transpose_split_kernel<<<dim3(64, 64), tb>>>(f2kw, wt + OFF_F2K, 2048, 2048);
    transpose_split_kernel<<<dim3(64, 64), tb>>>(f2vw, wt + OFF_F2V, 2048, 2048);
    transpose_split_kernel<<<dim3(16, 16), tb>>>(f2ow, wt + OFF_F2O, 512,  512);
    convert_kernel<<<4096, 256>>>(x, x_sp, (int)S);

    // ---- graph attention (q,k,scores near-exact blocked-compensated fp32) ----
    kgemm_kernel<<<kg, blk>>>(x, aqw, aqb, qb, NROWS, 512, 512, 1);
    kgemm_kernel<<<kg, blk>>>(x, akw, akb, kb, NROWS, 512, 512, 0);
    mm_gemm_kernel<1,0><<<tg512, blk, MM_SMEM>>>(x_sp, wt + OFF_AV, avb, nullptr, vb, NROWS, 512, 512);
    scores_kernel<<<dim3(11, 11, 512), blk>>>(qb, kb, Aout);
    topk_softmax_kernel<<<20544, blk>>>(Aout);
    av_kernel<<<dim3(1, 6, 512), blk>>>(Aout, vb, att_sp);
    mm_gemm_kernel<2,1><<<tg512, blk, MM_SMEM>>>(att_sp, wt + OFF_AO, aob, x, zb_sp, NROWS, 512, 512);
    mm_gemm_kernel<0,1><<<tg512, blk, MM_SMEM>>>(zb_sp, wt + OFF_ENC, encb, nullptr, y2_sp, NROWS, 512, 512);

    // ---- ff1 pwattn ----
    mm_gemm_kernel<1,0><<<tg2048, blk, MM_SMEM>>>(y2_sp, wt + OFF_F1Q, f1qb, nullptr, q1, NROWS, 2048, 512);
    mm_gemm_kernel<0,0><<<tg512, blk, MM_SMEM>>>(y2_sp, wt + OFF_F1K, f1kb, nullptr, k1, NROWS, 512, 512);
    mm_gemm_kernel<1,0><<<tg512, blk, MM_SMEM>>>(y2_sp, wt + OFF_F1V, f1vb, nullptr, v1, NROWS, 512, 512);
    pwattn1_kernel<<<NROWS, 128>>>(q1, k1, v1, Vf1_sp);
    mm_gemm_kernel<3,0><<<tg2048, blk, MM_SMEM>>>(Vf1_sp, wt + OFF_F1O, f1ob, q1, t1, NROWS, 2048, 2048);
    ln_kernel<<<NROWS, blk>>>(t1, lng, lnb, u_sp);

    // ---- ff2 pwattn ----
    mm_gemm_kernel<1,0><<<tg512, blk, MM_SMEM>>>(u_sp, wt + OFF_F2Q, f2qb, nullptr, qu2, NROWS, 512, 2048);
    mm_gemm_kernel<0,0><<<tg2048, blk, MM_SMEM>>>(u_sp, wt + OFF_F2K, f2kb, nullptr, q1, NROWS, 2048, 2048);
    mm_gemm_kernel<1,0><<<tg2048, blk, MM_SMEM>>>(u_sp, wt + OFF_F2V, f2vb, nullptr, v2, NROWS, 2048, 2048);
    pwattn2_kernel<<<NROWS / 4, 128>>>(qu2, q1, v2, x_sp);
    mm_gemm_kernel<4,0><<<tg512, blk, MM_SMEM>>>(x_sp, wt + OFF_F2O, f2ob, qu2, out, NROWS, 512, 512);
}